// round 1
// baseline (speedup 1.0000x reference)
#include <cuda_runtime.h>
#include <cstdint>
#include <cstddef>

#define NN 50000
#define EE 800000
#define ET (EE + NN)

// ---------------- scratch (device globals; no allocation allowed) ----------
__device__ __align__(16) float g_xp1[(size_t)NN * 256];   // x_noised @ W1
__device__ __align__(16) float g_h[(size_t)NN * 256];     // elu(layer1 out)
__device__ __align__(16) float g_hs[(size_t)NN * 256];    // relu(x_clean@W1+b1)
__device__ __align__(16) float g_xp2[(size_t)NN * 64];    // h @ W2
__device__ __align__(16) float g_skip[(size_t)NN * 64];   // hs @ W2 + b2
__device__ __align__(16) float g_als1[NN * 4];
__device__ __align__(16) float g_ald1[NN * 4];
__device__ __align__(16) float g_als2[NN];
__device__ __align__(16) float g_ald2[NN];
__device__ int g_deg[NN];
__device__ int g_offs[NN + 1];
__device__ int g_cur[NN];
__device__ int g_ssrc[ET];

// ---------------- CSR build ------------------------------------------------
__global__ void init_deg_kernel(int n) {
    int i = blockIdx.x * blockDim.x + threadIdx.x;
    if (i < n) g_deg[i] = 1;  // self-loop
}

__global__ void count_kernel(const int* __restrict__ edst, int e) {
    int i = blockIdx.x * blockDim.x + threadIdx.x;
    if (i < e) atomicAdd(&g_deg[edst[i]], 1);
}

// single-block exclusive scan over g_deg -> g_offs (n up to ~50k)
__global__ void scan_kernel(int n) {
    __shared__ int wsum[32];
    __shared__ int s_carry;
    int tid = threadIdx.x, lane = tid & 31, wid = tid >> 5;
    if (tid == 0) s_carry = 0;
    __syncthreads();
    for (int base = 0; base < n; base += 1024) {
        int i = base + tid;
        int v = (i < n) ? g_deg[i] : 0;
        int x = v;
        #pragma unroll
        for (int o = 1; o < 32; o <<= 1) {
            int y = __shfl_up_sync(0xffffffffu, x, o);
            if (lane >= o) x += y;
        }
        if (lane == 31) wsum[wid] = x;
        __syncthreads();
        if (wid == 0) {
            int w = wsum[lane];
            #pragma unroll
            for (int o = 1; o < 32; o <<= 1) {
                int y = __shfl_up_sync(0xffffffffu, w, o);
                if (lane >= o) w += y;
            }
            wsum[lane] = w;
        }
        __syncthreads();
        int excl = s_carry + (wid > 0 ? wsum[wid - 1] : 0) + x - v;
        if (i < n) g_offs[i] = excl;
        __syncthreads();
        if (tid == 0) s_carry += wsum[31];
        __syncthreads();
    }
    if (tid == 0) g_offs[n] = s_carry;
}

__global__ void place_kernel(int n) {
    int i = blockIdx.x * blockDim.x + threadIdx.x;
    if (i < n) {
        int o = g_offs[i];
        g_ssrc[o] = i;        // self-loop first (deterministic)
        g_cur[i] = o + 1;
    }
}

__global__ void scatter_kernel(const int* __restrict__ esrc,
                               const int* __restrict__ edst, int e) {
    int i = blockIdx.x * blockDim.x + threadIdx.x;
    if (i < e) {
        int d = edst[i];
        int pos = atomicAdd(&g_cur[d], 1);
        g_ssrc[pos] = esrc[i];
    }
}

// ---------------- GEMM (M x 256) @ (256 x NC), fp32 SIMT -------------------
// EPI: 0 = none, 1 = +bias then relu, 2 = +bias
template <int EPI>
__global__ void gemm256(const float* __restrict__ Aext, int asel,
                        const float* __restrict__ B,
                        const float* __restrict__ bias,
                        int csel, float* __restrict__ Cext,
                        int M, int NC) {
    const float* A = (asel == 0) ? Aext : (asel == 1) ? g_hs : g_h;
    float* C = (csel == 0) ? Cext
             : (csel == 1) ? g_xp1
             : (csel == 2) ? g_hs
             : (csel == 3) ? g_skip
                           : g_xp2;
    __shared__ float As[16][128];
    __shared__ float Bs[16][64];
    int tid = threadIdx.x;
    int m0 = blockIdx.x * 128;
    int n0 = blockIdx.y * 64;
    int ty = tid >> 4, tx = tid & 15;
    float acc[8][4];
    #pragma unroll
    for (int i = 0; i < 8; i++)
        #pragma unroll
        for (int j = 0; j < 4; j++) acc[i][j] = 0.f;

    int a_row = tid >> 2;
    int a_kq = (tid & 3) << 2;
    int b_row = tid >> 4;
    int b_col = (tid & 15) << 2;

    for (int k0 = 0; k0 < 256; k0 += 16) {
        #pragma unroll
        for (int r = 0; r < 2; r++) {
            int row = a_row + r * 64;
            float4 v = make_float4(0.f, 0.f, 0.f, 0.f);
            if (m0 + row < M)
                v = *reinterpret_cast<const float4*>(
                    &A[(size_t)(m0 + row) * 256 + k0 + a_kq]);
            As[a_kq + 0][row] = v.x;
            As[a_kq + 1][row] = v.y;
            As[a_kq + 2][row] = v.z;
            As[a_kq + 3][row] = v.w;
        }
        *reinterpret_cast<float4*>(&Bs[b_row][b_col]) =
            *reinterpret_cast<const float4*>(&B[(size_t)(k0 + b_row) * NC + n0 + b_col]);
        __syncthreads();
        #pragma unroll
        for (int kk = 0; kk < 16; kk++) {
            float4 a0 = *reinterpret_cast<const float4*>(&As[kk][ty * 8]);
            float4 a1 = *reinterpret_cast<const float4*>(&As[kk][ty * 8 + 4]);
            float4 bv = *reinterpret_cast<const float4*>(&Bs[kk][tx * 4]);
            float af[8] = {a0.x, a0.y, a0.z, a0.w, a1.x, a1.y, a1.z, a1.w};
            float bf[4] = {bv.x, bv.y, bv.z, bv.w};
            #pragma unroll
            for (int i = 0; i < 8; i++)
                #pragma unroll
                for (int j = 0; j < 4; j++)
                    acc[i][j] = fmaf(af[i], bf[j], acc[i][j]);
        }
        __syncthreads();
    }
    #pragma unroll
    for (int i = 0; i < 8; i++) {
        int row = m0 + ty * 8 + i;
        if (row >= M) continue;
        int col = n0 + tx * 4;
        float4 v = make_float4(acc[i][0], acc[i][1], acc[i][2], acc[i][3]);
        if (EPI) {
            v.x += bias[col + 0];
            v.y += bias[col + 1];
            v.z += bias[col + 2];
            v.w += bias[col + 3];
            if (EPI == 1) {
                v.x = fmaxf(v.x, 0.f);
                v.y = fmaxf(v.y, 0.f);
                v.z = fmaxf(v.z, 0.f);
                v.w = fmaxf(v.w, 0.f);
            }
        }
        *reinterpret_cast<float4*>(&C[(size_t)row * NC + col]) = v;
    }
}

// ---------------- attention logits: al[n,h] = <xp[n,h,:], a[h,:]> ----------
__global__ void al_kernel(const float* __restrict__ asrc,
                          const float* __restrict__ adst,
                          int sel, int n, int H) {
    int t = blockIdx.x * blockDim.x + threadIdx.x;
    if (t >= n * H) return;
    const float* xp = sel ? g_xp2 : g_xp1;
    float* als = sel ? g_als2 : g_als1;
    float* ald = sel ? g_ald2 : g_ald1;
    int h = t % H;
    const float4* xr = reinterpret_cast<const float4*>(xp + (size_t)t * 64);
    const float4* a4 = reinterpret_cast<const float4*>(asrc + h * 64);
    const float4* d4 = reinterpret_cast<const float4*>(adst + h * 64);
    float s1 = 0.f, s2 = 0.f;
    #pragma unroll
    for (int q = 0; q < 16; q++) {
        float4 x = xr[q], a = a4[q], d = d4[q];
        s1 += x.x * a.x + x.y * a.y + x.z * a.z + x.w * a.w;
        s2 += x.x * d.x + x.y * d.y + x.z * d.z + x.w * d.w;
    }
    als[t] = s1;
    ald[t] = s2;
}

// ---------------- layer1 aggregation: warp per (node, head), online softmax
__global__ void agg1_kernel(const float* __restrict__ b1) {
    int node = blockIdx.x;
    int h = threadIdx.x >> 5;
    int lane = threadIdx.x & 31;
    int beg = g_offs[node], end = g_offs[node + 1];
    float adn = g_ald1[node * 4 + h];
    float m = -1e30f, ssum = 0.f, ax = 0.f, ay = 0.f;
    for (int j = beg; j < end; j++) {
        int s = g_ssrc[j];
        float a = g_als1[s * 4 + h] + adn;
        a = (a > 0.f) ? a : 0.2f * a;
        if (a > m) {
            float sc = __expf(m - a);
            ax *= sc; ay *= sc; ssum *= sc; m = a;
        }
        float w = __expf(a - m);
        ssum += w;
        float2 v = *reinterpret_cast<const float2*>(
            &g_xp1[(size_t)s * 256 + h * 64 + lane * 2]);
        ax = fmaf(w, v.x, ax);
        ay = fmaf(w, v.y, ay);
    }
    float inv = 1.f / ssum;
    int col = h * 64 + lane * 2;
    float o0 = ax * inv + b1[col];
    float o1 = ay * inv + b1[col + 1];
    o0 = (o0 > 0.f) ? o0 : expm1f(o0);  // elu
    o1 = (o1 > 0.f) ? o1 : expm1f(o1);
    g_h[(size_t)node * 256 + col] = o0;
    g_h[(size_t)node * 256 + col + 1] = o1;
}

// ---------------- layer2 aggregation: warp per node, + b2 + skip -> out ----
__global__ void agg2_kernel(const float* __restrict__ b2,
                            float* __restrict__ out, int n) {
    int node = blockIdx.x * 4 + (threadIdx.x >> 5);
    if (node >= n) return;
    int lane = threadIdx.x & 31;
    int beg = g_offs[node], end = g_offs[node + 1];
    float adn = g_ald2[node];
    float m = -1e30f, ssum = 0.f, ax = 0.f, ay = 0.f;
    for (int j = beg; j < end; j++) {
        int s = g_ssrc[j];
        float a = g_als2[s] + adn;
        a = (a > 0.f) ? a : 0.2f * a;
        if (a > m) {
            float sc = __expf(m - a);
            ax *= sc; ay *= sc; ssum *= sc; m = a;
        }
        float w = __expf(a - m);
        ssum += w;
        float2 v = *reinterpret_cast<const float2*>(&g_xp2[(size_t)s * 64 + lane * 2]);
        ax = fmaf(w, v.x, ax);
        ay = fmaf(w, v.y, ay);
    }
    float inv = 1.f / ssum;
    int col = lane * 2;
    out[(size_t)node * 64 + col] =
        ax * inv + b2[col] + g_skip[(size_t)node * 64 + col];
    out[(size_t)node * 64 + col + 1] =
        ay * inv + b2[col + 1] + g_skip[(size_t)node * 64 + col + 1];
}

// ---------------- launch ---------------------------------------------------
extern "C" void kernel_launch(void* const* d_in, const int* in_sizes, int n_in,
                              void* d_out, int out_size) {
    const float* x_clean  = (const float*)d_in[0];
    const float* x_noised = (const float*)d_in[1];
    const int*   esrc     = (const int*)d_in[2];
    const int*   edst     = (const int*)d_in[3];
    const float* W1  = (const float*)d_in[4];
    const float* as1 = (const float*)d_in[5];
    const float* ad1 = (const float*)d_in[6];
    const float* b1  = (const float*)d_in[7];
    const float* W2  = (const float*)d_in[8];
    const float* as2 = (const float*)d_in[9];
    const float* ad2 = (const float*)d_in[10];
    const float* b2  = (const float*)d_in[11];
    float* out = (float*)d_out;

    int N = in_sizes[0] / 256;  // 50000
    int E = in_sizes[2];        // 800000

    // CSR build (dst-sorted adjacency, self-loop first per node)
    init_deg_kernel<<<(N + 255) / 256, 256>>>(N);
    count_kernel<<<(E + 255) / 256, 256>>>(edst, E);
    scan_kernel<<<1, 1024>>>(N);
    place_kernel<<<(N + 255) / 256, 256>>>(N);
    scatter_kernel<<<(E + 255) / 256, 256>>>(esrc, edst, E);

    dim3 gA((N + 127) / 128, 4);  // NC=256
    dim3 gB((N + 127) / 128, 1);  // NC=64

    // main + skip GEMMs
    gemm256<0><<<gA, 256>>>(x_noised, 0, W1, nullptr, 1, nullptr, N, 256);  // xp1
    gemm256<1><<<gA, 256>>>(x_clean, 0, W1, b1, 2, nullptr, N, 256);        // hs = relu(.+b1)
    gemm256<2><<<gB, 256>>>(nullptr, 1, W2, b2, 3, nullptr, N, 64);         // skip = hs@W2+b2

    // layer 1: logits, softmax-aggregate, elu -> h
    al_kernel<<<(N * 4 + 255) / 256, 256>>>(as1, ad1, 0, N, 4);
    agg1_kernel<<<N, 128>>>(b1);

    // layer 2: GEMM, logits, aggregate (+b2 +skip) -> out
    gemm256<0><<<gB, 256>>>(nullptr, 2, W2, nullptr, 4, nullptr, N, 64);    // xp2
    al_kernel<<<(N + 255) / 256, 256>>>(as2, ad2, 1, N, 1);
    agg2_kernel<<<(N + 3) / 4, 128>>>(b2, out, N);
}

// round 2
// speedup vs baseline: 1.4955x; 1.4955x over previous
#include <cuda_runtime.h>
#include <cstdint>
#include <cstddef>

#define NN 50000
#define EE 800000
#define ET (EE + NN)

// ---------------- scratch (device globals; no allocation allowed) ----------
__device__ __align__(16) float g_xp1[(size_t)NN * 256];   // x_noised @ W1
__device__ __align__(16) float g_h[(size_t)NN * 256];     // elu(layer1 out)
__device__ __align__(16) float g_hs[(size_t)NN * 256];    // relu(x_clean@W1+b1)
__device__ __align__(16) float g_xp2[(size_t)NN * 64];    // h @ W2
__device__ __align__(16) float g_skip[(size_t)NN * 64];   // hs @ W2 + b2
__device__ __align__(16) float g_als1[NN * 4];
__device__ __align__(16) float g_ald1[NN * 4];
__device__ __align__(16) float g_als2[NN];
__device__ __align__(16) float g_ald2[NN];
__device__ int g_deg[NN];
__device__ int g_offs[NN + 1];
__device__ int g_cur[NN];
__device__ int g_ssrc[ET];

// ---------------- CSR build ------------------------------------------------
__global__ void init_deg_kernel(int n) {
    int i = blockIdx.x * blockDim.x + threadIdx.x;
    if (i < n) g_deg[i] = 1;  // self-loop
}

__global__ void count_kernel(const int* __restrict__ edst, int e) {
    int i = blockIdx.x * blockDim.x + threadIdx.x;
    if (i < e) atomicAdd(&g_deg[edst[i]], 1);
}

// single-block exclusive scan over g_deg -> g_offs
__global__ void scan_kernel(int n) {
    __shared__ int wsum[32];
    __shared__ int s_carry;
    int tid = threadIdx.x, lane = tid & 31, wid = tid >> 5;
    if (tid == 0) s_carry = 0;
    __syncthreads();
    for (int base = 0; base < n; base += 1024) {
        int i = base + tid;
        int v = (i < n) ? g_deg[i] : 0;
        int x = v;
        #pragma unroll
        for (int o = 1; o < 32; o <<= 1) {
            int y = __shfl_up_sync(0xffffffffu, x, o);
            if (lane >= o) x += y;
        }
        if (lane == 31) wsum[wid] = x;
        __syncthreads();
        if (wid == 0) {
            int w = wsum[lane];
            #pragma unroll
            for (int o = 1; o < 32; o <<= 1) {
                int y = __shfl_up_sync(0xffffffffu, w, o);
                if (lane >= o) w += y;
            }
            wsum[lane] = w;
        }
        __syncthreads();
        int excl = s_carry + (wid > 0 ? wsum[wid - 1] : 0) + x - v;
        if (i < n) g_offs[i] = excl;
        __syncthreads();
        if (tid == 0) s_carry += wsum[31];
        __syncthreads();
    }
    if (tid == 0) g_offs[n] = s_carry;
}

__global__ void place_kernel(int n) {
    int i = blockIdx.x * blockDim.x + threadIdx.x;
    if (i < n) {
        int o = g_offs[i];
        g_ssrc[o] = i;        // self-loop first
        g_cur[i] = o + 1;
    }
}

__global__ void scatter_kernel(const int* __restrict__ esrc,
                               const int* __restrict__ edst, int e) {
    int i = blockIdx.x * blockDim.x + threadIdx.x;
    if (i < e) {
        int d = edst[i];
        int pos = atomicAdd(&g_cur[d], 1);
        g_ssrc[pos] = esrc[i];
    }
}

// ---------------- TF32 tensor-core GEMM ------------------------------------
// C[M,NC] = A[M,256] @ B[256,NC], tile 128x64x32, 8 warps.
__device__ __forceinline__ unsigned f2tf32(float x) {
    unsigned r;
    asm("cvt.rna.tf32.f32 %0, %1;" : "=r"(r) : "f"(x));
    return r;
}

__device__ __forceinline__ void mma_tf32(float* c, const unsigned* a,
                                         const unsigned* b) {
    asm volatile(
        "mma.sync.aligned.m16n8k8.row.col.f32.tf32.tf32.f32 "
        "{%0,%1,%2,%3}, {%4,%5,%6,%7}, {%8,%9}, {%0,%1,%2,%3};\n"
        : "+f"(c[0]), "+f"(c[1]), "+f"(c[2]), "+f"(c[3])
        : "r"(a[0]), "r"(a[1]), "r"(a[2]), "r"(a[3]), "r"(b[0]), "r"(b[1]));
}

// EPI: 0 = none, 1 = +bias then relu, 2 = +bias
template <int EPI>
__global__ void gemm_tc(const float* __restrict__ Aext, int asel,
                        const float* __restrict__ B,
                        const float* __restrict__ bias,
                        int csel, float* __restrict__ Cext,
                        int M, int NC) {
    const float* A = (asel == 0) ? Aext : (asel == 1) ? g_hs : g_h;
    float* C = (csel == 0) ? Cext
             : (csel == 1) ? g_xp1
             : (csel == 2) ? g_hs
             : (csel == 3) ? g_skip
                           : g_xp2;

    __shared__ unsigned As[128][36];  // stride 36: frag addr = 4g+t, conflict-free
    __shared__ unsigned Bs[32][72];   // stride 72: frag addr = 8t+g, conflict-free

    int tid = threadIdx.x;
    int wid = tid >> 5, lane = tid & 31;
    int g = lane >> 2, t4 = lane & 3;
    int wm = (wid >> 1) * 32;  // warp m offset within 128
    int wn = (wid & 1) * 32;   // warp n offset within 64
    int m0 = blockIdx.x * 128;
    int n0 = blockIdx.y * 64;

    float acc[2][4][4];
    #pragma unroll
    for (int mt = 0; mt < 2; mt++)
        #pragma unroll
        for (int nt = 0; nt < 4; nt++)
            #pragma unroll
            for (int q = 0; q < 4; q++) acc[mt][nt][q] = 0.f;

    for (int k0 = 0; k0 < 256; k0 += 32) {
        // load A tile: 128 rows x 32 k = 1024 float4, 4 per thread
        #pragma unroll
        for (int i = 0; i < 4; i++) {
            int linear = tid + i * 256;            // 0..1023
            int row = linear >> 3;
            int kq = (linear & 7) << 2;
            float4 v = make_float4(0.f, 0.f, 0.f, 0.f);
            if (m0 + row < M)
                v = *reinterpret_cast<const float4*>(
                    &A[(size_t)(m0 + row) * 256 + k0 + kq]);
            uint4 u = make_uint4(f2tf32(v.x), f2tf32(v.y), f2tf32(v.z), f2tf32(v.w));
            *reinterpret_cast<uint4*>(&As[row][kq]) = u;
        }
        // load B tile: 32 k x 64 n = 512 float4, 2 per thread
        #pragma unroll
        for (int i = 0; i < 2; i++) {
            int linear = tid + i * 256;            // 0..511
            int kr = linear >> 4;
            int nq = (linear & 15) << 2;
            float4 v = *reinterpret_cast<const float4*>(
                &B[(size_t)(k0 + kr) * NC + n0 + nq]);
            uint4 u = make_uint4(f2tf32(v.x), f2tf32(v.y), f2tf32(v.z), f2tf32(v.w));
            *reinterpret_cast<uint4*>(&Bs[kr][nq]) = u;
        }
        __syncthreads();

        #pragma unroll
        for (int kk = 0; kk < 4; kk++) {
            int kb = kk * 8;
            unsigned a[2][4], b[4][2];
            #pragma unroll
            for (int mt = 0; mt < 2; mt++) {
                int r = wm + mt * 16 + g;
                a[mt][0] = As[r][kb + t4];
                a[mt][1] = As[r + 8][kb + t4];
                a[mt][2] = As[r][kb + t4 + 4];
                a[mt][3] = As[r + 8][kb + t4 + 4];
            }
            #pragma unroll
            for (int nt = 0; nt < 4; nt++) {
                int n = wn + nt * 8 + g;
                b[nt][0] = Bs[kb + t4][n];
                b[nt][1] = Bs[kb + t4 + 4][n];
            }
            #pragma unroll
            for (int mt = 0; mt < 2; mt++)
                #pragma unroll
                for (int nt = 0; nt < 4; nt++)
                    mma_tf32(acc[mt][nt], a[mt], b[nt]);
        }
        __syncthreads();
    }

    // epilogue: c0,c1 -> (row, 2t),(row, 2t+1); c2,c3 -> (row+8, ...)
    #pragma unroll
    for (int mt = 0; mt < 2; mt++) {
        #pragma unroll
        for (int half = 0; half < 2; half++) {
            int row = m0 + wm + mt * 16 + g + half * 8;
            if (row >= M) continue;
            #pragma unroll
            for (int nt = 0; nt < 4; nt++) {
                int col = n0 + wn + nt * 8 + 2 * t4;
                float v0 = acc[mt][nt][half * 2 + 0];
                float v1 = acc[mt][nt][half * 2 + 1];
                if (EPI) {
                    v0 += bias[col];
                    v1 += bias[col + 1];
                    if (EPI == 1) {
                        v0 = fmaxf(v0, 0.f);
                        v1 = fmaxf(v1, 0.f);
                    }
                }
                float2 o = make_float2(v0, v1);
                *reinterpret_cast<float2*>(&C[(size_t)row * NC + col]) = o;
            }
        }
    }
}

// ---------------- attention logits: al[n,h] = <xp[n,h,:], a[h,:]> ----------
__global__ void al_kernel(const float* __restrict__ asrc,
                          const float* __restrict__ adst,
                          int sel, int n, int H) {
    int t = blockIdx.x * blockDim.x + threadIdx.x;
    if (t >= n * H) return;
    const float* xp = sel ? g_xp2 : g_xp1;
    float* als = sel ? g_als2 : g_als1;
    float* ald = sel ? g_ald2 : g_ald1;
    int h = t % H;
    const float4* xr = reinterpret_cast<const float4*>(xp + (size_t)t * 64);
    const float4* a4 = reinterpret_cast<const float4*>(asrc + h * 64);
    const float4* d4 = reinterpret_cast<const float4*>(adst + h * 64);
    float s1 = 0.f, s2 = 0.f;
    #pragma unroll
    for (int q = 0; q < 16; q++) {
        float4 x = xr[q], a = a4[q], d = d4[q];
        s1 += x.x * a.x + x.y * a.y + x.z * a.z + x.w * a.w;
        s2 += x.x * d.x + x.y * d.y + x.z * d.z + x.w * d.w;
    }
    als[t] = s1;
    ald[t] = s2;
}

// ---------------- layer1 aggregation: warp per (node, head), online softmax
__global__ void agg1_kernel(const float* __restrict__ b1) {
    int node = blockIdx.x;
    int h = threadIdx.x >> 5;
    int lane = threadIdx.x & 31;
    int beg = g_offs[node], end = g_offs[node + 1];
    float adn = g_ald1[node * 4 + h];
    float m = -1e30f, ssum = 0.f, ax = 0.f, ay = 0.f;
    for (int j = beg; j < end; j++) {
        int s = g_ssrc[j];
        float a = g_als1[s * 4 + h] + adn;
        a = (a > 0.f) ? a : 0.2f * a;
        if (a > m) {
            float sc = __expf(m - a);
            ax *= sc; ay *= sc; ssum *= sc; m = a;
        }
        float w = __expf(a - m);
        ssum += w;
        float2 v = *reinterpret_cast<const float2*>(
            &g_xp1[(size_t)s * 256 + h * 64 + lane * 2]);
        ax = fmaf(w, v.x, ax);
        ay = fmaf(w, v.y, ay);
    }
    float inv = 1.f / ssum;
    int col = h * 64 + lane * 2;
    float o0 = ax * inv + b1[col];
    float o1 = ay * inv + b1[col + 1];
    o0 = (o0 > 0.f) ? o0 : expm1f(o0);  // elu
    o1 = (o1 > 0.f) ? o1 : expm1f(o1);
    g_h[(size_t)node * 256 + col] = o0;
    g_h[(size_t)node * 256 + col + 1] = o1;
}

// ---------------- layer2 aggregation: warp per node, + b2 + skip -> out ----
__global__ void agg2_kernel(const float* __restrict__ b2,
                            float* __restrict__ out, int n) {
    int node = blockIdx.x * 4 + (threadIdx.x >> 5);
    if (node >= n) return;
    int lane = threadIdx.x & 31;
    int beg = g_offs[node], end = g_offs[node + 1];
    float adn = g_ald2[node];
    float m = -1e30f, ssum = 0.f, ax = 0.f, ay = 0.f;
    for (int j = beg; j < end; j++) {
        int s = g_ssrc[j];
        float a = g_als2[s] + adn;
        a = (a > 0.f) ? a : 0.2f * a;
        if (a > m) {
            float sc = __expf(m - a);
            ax *= sc; ay *= sc; ssum *= sc; m = a;
        }
        float w = __expf(a - m);
        ssum += w;
        float2 v = *reinterpret_cast<const float2*>(&g_xp2[(size_t)s * 64 + lane * 2]);
        ax = fmaf(w, v.x, ax);
        ay = fmaf(w, v.y, ay);
    }
    float inv = 1.f / ssum;
    int col = lane * 2;
    out[(size_t)node * 64 + col] =
        ax * inv + b2[col] + g_skip[(size_t)node * 64 + col];
    out[(size_t)node * 64 + col + 1] =
        ay * inv + b2[col + 1] + g_skip[(size_t)node * 64 + col + 1];
}

// ---------------- launch ---------------------------------------------------
extern "C" void kernel_launch(void* const* d_in, const int* in_sizes, int n_in,
                              void* d_out, int out_size) {
    const float* x_clean  = (const float*)d_in[0];
    const float* x_noised = (const float*)d_in[1];
    const int*   esrc     = (const int*)d_in[2];
    const int*   edst     = (const int*)d_in[3];
    const float* W1  = (const float*)d_in[4];
    const float* as1 = (const float*)d_in[5];
    const float* ad1 = (const float*)d_in[6];
    const float* b1  = (const float*)d_in[7];
    const float* W2  = (const float*)d_in[8];
    const float* as2 = (const float*)d_in[9];
    const float* ad2 = (const float*)d_in[10];
    const float* b2  = (const float*)d_in[11];
    float* out = (float*)d_out;

    int N = in_sizes[0] / 256;  // 50000
    int E = in_sizes[2];        // 800000

    // CSR build (dst-sorted adjacency, self-loop first per node)
    init_deg_kernel<<<(N + 255) / 256, 256>>>(N);
    count_kernel<<<(E + 255) / 256, 256>>>(edst, E);
    scan_kernel<<<1, 1024>>>(N);
    place_kernel<<<(N + 255) / 256, 256>>>(N);
    scatter_kernel<<<(E + 255) / 256, 256>>>(esrc, edst, E);

    dim3 gA((N + 127) / 128, 4);  // NC=256
    dim3 gB((N + 127) / 128, 1);  // NC=64

    // main + skip GEMMs (TF32 tensor cores)
    gemm_tc<0><<<gA, 256>>>(x_noised, 0, W1, nullptr, 1, nullptr, N, 256);  // xp1
    gemm_tc<1><<<gA, 256>>>(x_clean, 0, W1, b1, 2, nullptr, N, 256);        // hs
    gemm_tc<2><<<gB, 256>>>(nullptr, 1, W2, b2, 3, nullptr, N, 64);         // skip

    // layer 1: logits, softmax-aggregate, elu -> h
    al_kernel<<<(N * 4 + 255) / 256, 256>>>(as1, ad1, 0, N, 4);
    agg1_kernel<<<N, 128>>>(b1);

    // layer 2: GEMM, logits, aggregate (+b2 +skip) -> out
    gemm_tc<0><<<gB, 256>>>(nullptr, 2, W2, nullptr, 4, nullptr, N, 64);    // xp2
    al_kernel<<<(N + 255) / 256, 256>>>(as2, ad2, 1, N, 1);
    agg2_kernel<<<(N + 3) / 4, 128>>>(b2, out, N);
}

// round 4
// speedup vs baseline: 2.0924x; 1.3991x over previous
#include <cuda_runtime.h>
#include <cstdint>
#include <cstddef>

#define NN 50000
#define EE 800000
#define ET (EE + NN)

// ---------------- scratch (device globals; no allocation allowed) ----------
__device__ __align__(16) float g_xp1[(size_t)NN * 256];   // x_noised @ W1
__device__ __align__(16) float g_h[(size_t)NN * 256];     // elu(layer1 out)
__device__ __align__(16) float g_hs[(size_t)NN * 256];    // relu(x_clean@W1+b1)
__device__ __align__(16) float g_xp2[(size_t)NN * 64];    // h @ W2
__device__ __align__(16) float g_skip[(size_t)NN * 64];   // hs @ W2 + b2
__device__ __align__(16) float g_als1[NN * 4];
__device__ __align__(16) float g_ald1[NN * 4];
__device__ __align__(16) float g_als2[NN];
__device__ __align__(16) float g_ald2[NN];
__device__ int g_deg[NN];
__device__ int g_offs[NN + 1];
__device__ int g_cur[NN];
__device__ int g_ssrc[ET];
__device__ int g_bsum[256];
__device__ int g_bpre[256];

// ---------------- CSR build ------------------------------------------------
__global__ void init_deg_kernel(int n) {
    int i = blockIdx.x * blockDim.x + threadIdx.x;
    if (i < n) g_deg[i] = 1;  // self-loop
}

__global__ void count_kernel(const int* __restrict__ edst, int e) {
    int i = blockIdx.x * blockDim.x + threadIdx.x;
    if (i < e) atomicAdd(&g_deg[edst[i]], 1);
}

__global__ void scan_local_kernel(int n) {
    __shared__ int ws[9];
    int tid = threadIdx.x, lane = tid & 31, w = tid >> 5;
    int i = blockIdx.x * 256 + tid;
    int v = (i < n) ? g_deg[i] : 0;
    int x = v;
    #pragma unroll
    for (int o = 1; o < 32; o <<= 1) {
        int y = __shfl_up_sync(0xffffffffu, x, o);
        if (lane >= o) x += y;
    }
    if (lane == 31) ws[w] = x;
    __syncthreads();
    if (tid == 0) {
        int s = 0;
        #pragma unroll
        for (int q = 0; q < 8; q++) { int t = ws[q]; ws[q] = s; s += t; }
        g_bsum[blockIdx.x] = s;
    }
    __syncthreads();
    if (i < n) g_offs[i] = ws[w] + x - v;
}

__global__ void scan_bsum_kernel(int nb, int n) {
    __shared__ int sh[256];
    int tid = threadIdx.x;
    int v = (tid < nb) ? g_bsum[tid] : 0;
    sh[tid] = v;
    __syncthreads();
    for (int o = 1; o < 256; o <<= 1) {
        int t = (tid >= o) ? sh[tid - o] : 0;
        __syncthreads();
        sh[tid] += t;
        __syncthreads();
    }
    if (tid < nb) g_bpre[tid] = sh[tid] - v;
    if (tid == nb - 1) g_offs[n] = sh[tid];
}

__global__ void scan_add_kernel(int n) {
    int i = blockIdx.x * 256 + threadIdx.x;
    if (i < n && blockIdx.x > 0) g_offs[i] += g_bpre[blockIdx.x];
}

__global__ void place_kernel(int n) {
    int i = blockIdx.x * blockDim.x + threadIdx.x;
    if (i < n) {
        int o = g_offs[i];
        g_ssrc[o] = i;        // self-loop first
        g_cur[i] = o + 1;
    }
}

__global__ void scatter_kernel(const int* __restrict__ esrc,
                               const int* __restrict__ edst, int e) {
    int i = blockIdx.x * blockDim.x + threadIdx.x;
    if (i < e) {
        int d = edst[i];
        int pos = atomicAdd(&g_cur[d], 1);
        g_ssrc[pos] = esrc[i];
    }
}

// ---------------- TF32 tensor-core GEMM, double-buffered cp.async ----------
__device__ __forceinline__ unsigned f2tf32(float x) {
    unsigned r;
    asm("cvt.rna.tf32.f32 %0, %1;" : "=r"(r) : "f"(x));
    return r;
}
__device__ __forceinline__ uint32_t smem_u32(const void* p) {
    uint32_t a;
    asm("{ .reg .u64 t; cvta.to.shared.u64 t, %1; cvt.u32.u64 %0, t; }"
        : "=r"(a) : "l"(p));
    return a;
}
__device__ __forceinline__ void cp16(uint32_t dst, const void* src, int srcsz) {
    asm volatile("cp.async.cg.shared.global [%0], [%1], 16, %2;"
                 :: "r"(dst), "l"(src), "r"(srcsz));
}
__device__ __forceinline__ void cp_commit() {
    asm volatile("cp.async.commit_group;");
}
template <int N>
__device__ __forceinline__ void cp_wait() {
    asm volatile("cp.async.wait_group %0;" :: "n"(N));
}

__device__ __forceinline__ void mma_tf32(float* c, const unsigned* a,
                                         const unsigned* b) {
    asm volatile(
        "mma.sync.aligned.m16n8k8.row.col.f32.tf32.tf32.f32 "
        "{%0,%1,%2,%3}, {%4,%5,%6,%7}, {%8,%9}, {%0,%1,%2,%3};\n"
        : "+f"(c[0]), "+f"(c[1]), "+f"(c[2]), "+f"(c[3])
        : "r"(a[0]), "r"(a[1]), "r"(a[2]), "r"(a[3]), "r"(b[0]), "r"(b[1]));
}

// C[M,NC] = A[M,256] @ B[256,NC], tile 128x64x32, 8 warps, 2-stage pipeline.
// EPI: 0 = none, 1 = +bias relu, 2 = +bias
template <int EPI>
__global__ void __launch_bounds__(256) gemm_tc(
    const float* __restrict__ Aext, int asel,
    const float* __restrict__ B,
    const float* __restrict__ bias,
    int csel, int M, int NC) {
    const float* A = (asel == 0) ? Aext : (asel == 1) ? g_hs : g_h;
    float* C = (csel == 1) ? g_xp1
             : (csel == 2) ? g_hs
             : (csel == 3) ? g_skip
                           : g_xp2;

    // dynamic smem: As[2][128][36] + Bs[2][32][72] floats
    extern __shared__ float dynsm[];
    float* As = dynsm;                   // 2 * 4608
    float* Bs = dynsm + 2 * 128 * 36;    // 2 * 2304
    const int ASTG = 128 * 36, BSTG = 32 * 72;

    int tid = threadIdx.x;
    int wid = tid >> 5, lane = tid & 31;
    int g = lane >> 2, t4 = lane & 3;
    int wm = (wid >> 1) * 32;  // warp m offset within 128
    int wn = (wid & 1) * 32;   // warp n offset within 64
    int m0 = blockIdx.x * 128;
    int n0 = blockIdx.y * 64;

    uint32_t aA = smem_u32(As), aB = smem_u32(Bs);

    float acc[2][4][4];
    #pragma unroll
    for (int mt = 0; mt < 2; mt++)
        #pragma unroll
        for (int nt = 0; nt < 4; nt++)
            #pragma unroll
            for (int q = 0; q < 4; q++) acc[mt][nt][q] = 0.f;

    // per-thread load coords
    int a_row = tid >> 3;            // 0..31 (x4 iters -> 128 rows)... actually:
    // A chunk: 128 rows x 32 k = 1024 float4, 4/thread
    // lin = tid + i*256 ; row = lin>>3 ; kq = (lin&7)<<2
    // B chunk: 32 k x 64 n = 512 float4, 2/thread
    (void)a_row;

    auto load_chunk = [&](int ch, int st) {
        int k0 = ch * 32;
        #pragma unroll
        for (int i = 0; i < 4; i++) {
            int lin = tid + i * 256;
            int row = lin >> 3, kq = (lin & 7) << 2;
            uint32_t dst = aA + (uint32_t)(st * ASTG + row * 36 + kq) * 4u;
            const float* src = &A[(size_t)(m0 + row) * 256 + k0 + kq];
            cp16(dst, src, (m0 + row < M) ? 16 : 0);
        }
        #pragma unroll
        for (int i = 0; i < 2; i++) {
            int lin = tid + i * 256;
            int kr = lin >> 4, nq = (lin & 15) << 2;
            uint32_t dst = aB + (uint32_t)(st * BSTG + kr * 72 + nq) * 4u;
            const float* src = &B[(size_t)(k0 + kr) * NC + n0 + nq];
            cp16(dst, src, 16);
        }
        cp_commit();
    };

    load_chunk(0, 0);

    for (int ch = 0; ch < 8; ch++) {
        int st = ch & 1;
        if (ch < 7) {
            load_chunk(ch + 1, st ^ 1);
            cp_wait<1>();
        } else {
            cp_wait<0>();
        }
        __syncthreads();

        const float* Ast = As + st * ASTG;
        const float* Bst = Bs + st * BSTG;
        #pragma unroll
        for (int kk = 0; kk < 4; kk++) {
            int kb = kk * 8;
            unsigned a[2][4], b[4][2];
            #pragma unroll
            for (int mt = 0; mt < 2; mt++) {
                int r = wm + mt * 16 + g;
                a[mt][0] = f2tf32(Ast[r * 36 + kb + t4]);
                a[mt][1] = f2tf32(Ast[(r + 8) * 36 + kb + t4]);
                a[mt][2] = f2tf32(Ast[r * 36 + kb + t4 + 4]);
                a[mt][3] = f2tf32(Ast[(r + 8) * 36 + kb + t4 + 4]);
            }
            #pragma unroll
            for (int nt = 0; nt < 4; nt++) {
                int n = wn + nt * 8 + g;
                b[nt][0] = f2tf32(Bst[(kb + t4) * 72 + n]);
                b[nt][1] = f2tf32(Bst[(kb + t4 + 4) * 72 + n]);
            }
            #pragma unroll
            for (int mt = 0; mt < 2; mt++)
                #pragma unroll
                for (int nt = 0; nt < 4; nt++)
                    mma_tf32(acc[mt][nt], a[mt], b[nt]);
        }
        __syncthreads();  // protect stage st from next-next load
    }

    // epilogue
    #pragma unroll
    for (int mt = 0; mt < 2; mt++) {
        #pragma unroll
        for (int half = 0; half < 2; half++) {
            int row = m0 + wm + mt * 16 + g + half * 8;
            if (row >= M) continue;
            #pragma unroll
            for (int nt = 0; nt < 4; nt++) {
                int col = n0 + wn + nt * 8 + 2 * t4;
                float v0 = acc[mt][nt][half * 2 + 0];
                float v1 = acc[mt][nt][half * 2 + 1];
                if (EPI) {
                    v0 += bias[col];
                    v1 += bias[col + 1];
                    if (EPI == 1) {
                        v0 = fmaxf(v0, 0.f);
                        v1 = fmaxf(v1, 0.f);
                    }
                }
                float2 o = make_float2(v0, v1);
                *reinterpret_cast<float2*>(&C[(size_t)row * NC + col]) = o;
            }
        }
    }
}

// ---------------- attention logits -----------------------------------------
__global__ void al_kernel(const float* __restrict__ asrc,
                          const float* __restrict__ adst,
                          int sel, int n, int H) {
    int t = blockIdx.x * blockDim.x + threadIdx.x;
    if (t >= n * H) return;
    const float* xp = sel ? g_xp2 : g_xp1;
    float* als = sel ? g_als2 : g_als1;
    float* ald = sel ? g_ald2 : g_ald1;
    int h = t % H;
    const float4* xr = reinterpret_cast<const float4*>(xp + (size_t)t * 64);
    const float4* a4 = reinterpret_cast<const float4*>(asrc + h * 64);
    const float4* d4 = reinterpret_cast<const float4*>(adst + h * 64);
    float s1 = 0.f, s2 = 0.f;
    #pragma unroll
    for (int q = 0; q < 16; q++) {
        float4 x = xr[q], a = a4[q], d = d4[q];
        s1 += x.x * a.x + x.y * a.y + x.z * a.z + x.w * a.w;
        s2 += x.x * d.x + x.y * d.y + x.z * d.z + x.w * d.w;
    }
    als[t] = s1;
    ald[t] = s2;
}

// ---------------- layer1 aggregation: ONE warp per node, all 4 heads -------
__global__ void agg1_kernel(const float* __restrict__ b1, int n) {
    int node = blockIdx.x * 8 + (threadIdx.x >> 5);
    if (node >= n) return;
    int lane = threadIdx.x & 31;
    int h = lane >> 3;                 // lane's head (8 lanes per head)
    int beg = g_offs[node], end = g_offs[node + 1];
    float adn = g_ald1[node * 4 + h];
    float m = -1e30f, ssum = 0.f;
    float acc[8];
    #pragma unroll
    for (int q = 0; q < 8; q++) acc[q] = 0.f;

    for (int j = beg; j < end; j++) {
        int s = g_ssrc[j];
        float a = g_als1[s * 4 + h] + adn;
        a = (a > 0.f) ? a : 0.2f * a;
        if (a > m) {
            float sc = __expf(m - a);
            ssum *= sc;
            #pragma unroll
            for (int q = 0; q < 8; q++) acc[q] *= sc;
            m = a;
        }
        float w = __expf(a - m);
        ssum += w;
        const float4* row = reinterpret_cast<const float4*>(
            &g_xp1[(size_t)s * 256 + lane * 8]);
        float4 v0 = row[0], v1 = row[1];
        acc[0] = fmaf(w, v0.x, acc[0]);
        acc[1] = fmaf(w, v0.y, acc[1]);
        acc[2] = fmaf(w, v0.z, acc[2]);
        acc[3] = fmaf(w, v0.w, acc[3]);
        acc[4] = fmaf(w, v1.x, acc[4]);
        acc[5] = fmaf(w, v1.y, acc[5]);
        acc[6] = fmaf(w, v1.z, acc[6]);
        acc[7] = fmaf(w, v1.w, acc[7]);
    }
    float inv = 1.f / ssum;
    int col = lane * 8;
    float o[8];
    #pragma unroll
    for (int q = 0; q < 8; q++) {
        float x = acc[q] * inv + b1[col + q];
        o[q] = (x > 0.f) ? x : expm1f(x);   // elu
    }
    float4* dst = reinterpret_cast<float4*>(&g_h[(size_t)node * 256 + col]);
    dst[0] = make_float4(o[0], o[1], o[2], o[3]);
    dst[1] = make_float4(o[4], o[5], o[6], o[7]);
}

// ---------------- layer2 aggregation: warp per node ------------------------
__global__ void agg2_kernel(const float* __restrict__ b2,
                            float* __restrict__ out, int n) {
    int node = blockIdx.x * 8 + (threadIdx.x >> 5);
    if (node >= n) return;
    int lane = threadIdx.x & 31;
    int beg = g_offs[node], end = g_offs[node + 1];
    float adn = g_ald2[node];
    float m = -1e30f, ssum = 0.f, ax = 0.f, ay = 0.f;
    for (int j = beg; j < end; j++) {
        int s = g_ssrc[j];
        float a = g_als2[s] + adn;
        a = (a > 0.f) ? a : 0.2f * a;
        if (a > m) {
            float sc = __expf(m - a);
            ax *= sc; ay *= sc; ssum *= sc; m = a;
        }
        float w = __expf(a - m);
        ssum += w;
        float2 v = *reinterpret_cast<const float2*>(&g_xp2[(size_t)s * 64 + lane * 2]);
        ax = fmaf(w, v.x, ax);
        ay = fmaf(w, v.y, ay);
    }
    float inv = 1.f / ssum;
    int col = lane * 2;
    out[(size_t)node * 64 + col] =
        ax * inv + b2[col] + g_skip[(size_t)node * 64 + col];
    out[(size_t)node * 64 + col + 1] =
        ay * inv + b2[col + 1] + g_skip[(size_t)node * 64 + col + 1];
}

// ---------------- launch ---------------------------------------------------
extern "C" void kernel_launch(void* const* d_in, const int* in_sizes, int n_in,
                              void* d_out, int out_size) {
    const float* x_clean  = (const float*)d_in[0];
    const float* x_noised = (const float*)d_in[1];
    const int*   esrc     = (const int*)d_in[2];
    const int*   edst     = (const int*)d_in[3];
    const float* W1  = (const float*)d_in[4];
    const float* as1 = (const float*)d_in[5];
    const float* ad1 = (const float*)d_in[6];
    const float* b1  = (const float*)d_in[7];
    const float* W2  = (const float*)d_in[8];
    const float* as2 = (const float*)d_in[9];
    const float* ad2 = (const float*)d_in[10];
    const float* b2  = (const float*)d_in[11];
    float* out = (float*)d_out;

    int N = in_sizes[0] / 256;  // 50000
    int E = in_sizes[2];        // 800000

    const int SMB = (2 * 128 * 36 + 2 * 32 * 72) * 4;  // 55296 B
    cudaFuncSetAttribute(gemm_tc<0>, cudaFuncAttributeMaxDynamicSharedMemorySize, SMB);
    cudaFuncSetAttribute(gemm_tc<1>, cudaFuncAttributeMaxDynamicSharedMemorySize, SMB);
    cudaFuncSetAttribute(gemm_tc<2>, cudaFuncAttributeMaxDynamicSharedMemorySize, SMB);

    int nb = (N + 255) / 256;       // 196
    int mtiles = (N + 127) / 128;   // 391

    // Launch order chosen so the 6th launch (ncu -s 5 -c 1) is the hot GEMM.
    init_deg_kernel<<<nb, 256>>>(N);                      // 1
    count_kernel<<<(E + 255) / 256, 256>>>(edst, E);      // 2
    scan_local_kernel<<<nb, 256>>>(N);                    // 3
    scan_bsum_kernel<<<1, 256>>>(nb, N);                  // 4
    scan_add_kernel<<<nb, 256>>>(N);                      // 5
    gemm_tc<0><<<dim3(mtiles, 4), 256, SMB>>>(x_noised, 0, W1, nullptr, 1, N, 256);  // 6: xp1 (profiled)
    place_kernel<<<nb, 256>>>(N);                         // 7
    scatter_kernel<<<(E + 255) / 256, 256>>>(esrc, edst, E);  // 8
    gemm_tc<1><<<dim3(mtiles, 4), 256, SMB>>>(x_clean, 0, W1, b1, 2, N, 256);        // hs
    gemm_tc<2><<<dim3(mtiles, 1), 256, SMB>>>(nullptr, 1, W2, b2, 3, N, 64);         // skip

    // layer 1 attention
    al_kernel<<<(N * 4 + 255) / 256, 256>>>(as1, ad1, 0, N, 4);
    agg1_kernel<<<(N + 7) / 8, 256>>>(b1, N);

    // layer 2
    gemm_tc<0><<<dim3(mtiles, 1), 256, SMB>>>(nullptr, 2, W2, nullptr, 4, N, 64);    // xp2
    al_kernel<<<(N + 255) / 256, 256>>>(as2, ad2, 1, N, 1);
    agg2_kernel<<<(N + 7) / 8, 256>>>(b2, out, N);
}

// round 5
// speedup vs baseline: 2.4363x; 1.1644x over previous
#include <cuda_runtime.h>
#include <cuda_fp16.h>
#include <cstdint>
#include <cstddef>

#define NN 50000
#define EE 800000
#define ET (EE + NN)

// ---------------- scratch (device globals; no allocation allowed) ----------
__device__ __align__(16) float  g_xp1[(size_t)NN * 256];   // x_noised @ W1 (fp32, for agg gather)
__device__ __align__(16) float  g_xp2[(size_t)NN * 64];
__device__ __align__(16) float  g_skip[(size_t)NN * 64];
__device__ __align__(16) __half g_xa16[(size_t)NN * 256];  // fp16 x_noised
__device__ __align__(16) __half g_xc16[(size_t)NN * 256];  // fp16 x_clean
__device__ __align__(16) __half g_h16[(size_t)NN * 256];   // fp16 elu(layer1)
__device__ __align__(16) __half g_hs16[(size_t)NN * 256];  // fp16 relu(x_clean@W1+b1)
__device__ __align__(16) __half g_w1t16[256 * 256];        // W1^T fp16 [n][k]
__device__ __align__(16) __half g_w2t16[64 * 256];         // W2^T fp16 [n][k]
__device__ __align__(16) float g_als1[NN * 4];
__device__ __align__(16) float g_ald1[NN * 4];
__device__ __align__(16) float g_als2[NN];
__device__ __align__(16) float g_ald2[NN];
__device__ int g_deg[NN];
__device__ int g_offs[NN + 1];
__device__ int g_cur[NN];
__device__ int g_ssrc[ET];
__device__ int g_bsum[256];
__device__ int g_bpre[256];

// ---------------- fp16 conversion + weight transpose -----------------------
__global__ void cvt_kernel(const float* __restrict__ xn,
                           const float* __restrict__ xc,
                           const float* __restrict__ W1,
                           const float* __restrict__ W2) {
    int i = blockIdx.x * 256 + threadIdx.x;  // 3.2M float4 slots
    if (i < (NN * 256) / 4) {
        float4 a = reinterpret_cast<const float4*>(xn)[i];
        float4 b = reinterpret_cast<const float4*>(xc)[i];
        __half2 a0 = __floats2half2_rn(a.x, a.y);
        __half2 a1 = __floats2half2_rn(a.z, a.w);
        __half2 b0 = __floats2half2_rn(b.x, b.y);
        __half2 b1 = __floats2half2_rn(b.z, b.w);
        reinterpret_cast<__half2*>(g_xa16)[i * 2]     = a0;
        reinterpret_cast<__half2*>(g_xa16)[i * 2 + 1] = a1;
        reinterpret_cast<__half2*>(g_xc16)[i * 2]     = b0;
        reinterpret_cast<__half2*>(g_xc16)[i * 2 + 1] = b1;
    }
    if (i < 256 * 256) {
        int k = i >> 8, n = i & 255;
        g_w1t16[n * 256 + k] = __float2half_rn(W1[k * 256 + n]);
    }
    if (i < 256 * 64) {
        int k = i >> 6, n = i & 63;
        g_w2t16[n * 256 + k] = __float2half_rn(W2[k * 64 + n]);
    }
}

// ---------------- CSR build ------------------------------------------------
__global__ void init_deg_kernel(int n) {
    int i = blockIdx.x * blockDim.x + threadIdx.x;
    if (i < n) g_deg[i] = 1;
}

__global__ void count_kernel(const int* __restrict__ edst, int e) {
    int i = blockIdx.x * blockDim.x + threadIdx.x;
    if (i < e) atomicAdd(&g_deg[edst[i]], 1);
}

__global__ void scan_local_kernel(int n) {
    __shared__ int ws[9];
    int tid = threadIdx.x, lane = tid & 31, w = tid >> 5;
    int i = blockIdx.x * 256 + tid;
    int v = (i < n) ? g_deg[i] : 0;
    int x = v;
    #pragma unroll
    for (int o = 1; o < 32; o <<= 1) {
        int y = __shfl_up_sync(0xffffffffu, x, o);
        if (lane >= o) x += y;
    }
    if (lane == 31) ws[w] = x;
    __syncthreads();
    if (tid == 0) {
        int s = 0;
        #pragma unroll
        for (int q = 0; q < 8; q++) { int t = ws[q]; ws[q] = s; s += t; }
        g_bsum[blockIdx.x] = s;
    }
    __syncthreads();
    if (i < n) g_offs[i] = ws[w] + x - v;
}

__global__ void scan_bsum_kernel(int nb, int n) {
    __shared__ int wtot[8];
    int tid = threadIdx.x, lane = tid & 31, w = tid >> 5;
    int v = (tid < nb) ? g_bsum[tid] : 0;
    int x = v;
    #pragma unroll
    for (int o = 1; o < 32; o <<= 1) {
        int y = __shfl_up_sync(0xffffffffu, x, o);
        if (lane >= o) x += y;
    }
    if (lane == 31) wtot[w] = x;
    __syncthreads();
    int pre = 0;
    #pragma unroll
    for (int q = 0; q < 8; q++) pre += (q < w) ? wtot[q] : 0;
    if (tid < nb) g_bpre[tid] = pre + x - v;
    if (tid == nb - 1) g_offs[n] = pre + x;
}

__global__ void scan_add_kernel(int n) {
    int i = blockIdx.x * 256 + threadIdx.x;
    if (i < n && blockIdx.x > 0) g_offs[i] += g_bpre[blockIdx.x];
}

__global__ void place_kernel(int n) {
    int i = blockIdx.x * blockDim.x + threadIdx.x;
    if (i < n) {
        int o = g_offs[i];
        g_ssrc[o] = i;
        g_cur[i] = o + 1;
    }
}

__global__ void scatter_kernel(const int* __restrict__ esrc,
                               const int* __restrict__ edst, int e) {
    int i = blockIdx.x * blockDim.x + threadIdx.x;
    if (i < e) {
        int d = edst[i];
        int pos = atomicAdd(&g_cur[d], 1);
        g_ssrc[pos] = esrc[i];
    }
}

// ---------------- FP16 tensor-core GEMM, double-buffered cp.async ----------
__device__ __forceinline__ uint32_t smem_u32(const void* p) {
    uint32_t a;
    asm("{ .reg .u64 t; cvta.to.shared.u64 t, %1; cvt.u32.u64 %0, t; }"
        : "=r"(a) : "l"(p));
    return a;
}
__device__ __forceinline__ void cp16(uint32_t dst, const void* src, int srcsz) {
    asm volatile("cp.async.cg.shared.global [%0], [%1], 16, %2;"
                 :: "r"(dst), "l"(src), "r"(srcsz));
}
__device__ __forceinline__ void cp_commit() {
    asm volatile("cp.async.commit_group;");
}
template <int N>
__device__ __forceinline__ void cp_wait() {
    asm volatile("cp.async.wait_group %0;" :: "n"(N));
}
__device__ __forceinline__ void mma_f16(float* c, const unsigned* a,
                                        const unsigned* b) {
    asm volatile(
        "mma.sync.aligned.m16n8k16.row.col.f32.f16.f16.f32 "
        "{%0,%1,%2,%3}, {%4,%5,%6,%7}, {%8,%9}, {%0,%1,%2,%3};\n"
        : "+f"(c[0]), "+f"(c[1]), "+f"(c[2]), "+f"(c[3])
        : "r"(a[0]), "r"(a[1]), "r"(a[2]), "r"(a[3]), "r"(b[0]), "r"(b[1]));
}

// C[M,NC] = A16[M,256] @ B16t[NC,256]^T. Tile 128x64x64, 8 warps, 2 stages.
// EPI: 0 none, 1 +bias relu, 2 +bias. C16: write fp16.
template <int EPI, bool C16>
__global__ void __launch_bounds__(256) gemm_f16(
    int asel, int bsel, const float* __restrict__ bias, int csel, int M, int NC) {
    const __half* A = (asel == 0) ? g_xa16
                    : (asel == 1) ? g_xc16
                    : (asel == 2) ? g_hs16
                                  : g_h16;
    const __half* Bt = bsel ? g_w2t16 : g_w1t16;
    float* C = (csel == 1) ? g_xp1 : (csel == 3) ? g_skip : g_xp2;
    __half* Ch = g_hs16;

    // smem (halfs): As[2][128][72], Bs[2][64][72]
    extern __shared__ __half dynsm[];
    __half* As = dynsm;                  // 2 * 9216
    __half* Bs = dynsm + 2 * 128 * 72;   // 2 * 4608
    const int ASTG = 128 * 72, BSTG = 64 * 72;

    int tid = threadIdx.x;
    int wid = tid >> 5, lane = tid & 31;
    int g = lane >> 2, t4 = lane & 3;
    int wm = (wid >> 1) * 32;
    int wn = (wid & 1) * 32;
    int m0 = blockIdx.x * 128;
    int n0 = blockIdx.y * 64;

    uint32_t aA = smem_u32(As), aB = smem_u32(Bs);

    float acc[2][4][4];
    #pragma unroll
    for (int mt = 0; mt < 2; mt++)
        #pragma unroll
        for (int nt = 0; nt < 4; nt++)
            #pragma unroll
            for (int q = 0; q < 4; q++) acc[mt][nt][q] = 0.f;

    auto load_chunk = [&](int ch, int st) {
        int k0 = ch * 64;
        // A: 128 rows x 64 halfs = 1024 x 16B segs, 4/thread
        #pragma unroll
        for (int i = 0; i < 4; i++) {
            int lin = tid + i * 256;
            int row = lin >> 3, seg = lin & 7;
            uint32_t dst = aA + (uint32_t)(st * ASTG + row * 72 + seg * 8) * 2u;
            const __half* src = &A[(size_t)(m0 + row) * 256 + k0 + seg * 8];
            cp16(dst, src, (m0 + row < M) ? 16 : 0);
        }
        // B: 64 rows x 64 halfs = 512 segs, 2/thread
        #pragma unroll
        for (int i = 0; i < 2; i++) {
            int lin = tid + i * 256;
            int row = lin >> 3, seg = lin & 7;
            uint32_t dst = aB + (uint32_t)(st * BSTG + row * 72 + seg * 8) * 2u;
            const __half* src = &Bt[(size_t)(n0 + row) * 256 + k0 + seg * 8];
            cp16(dst, src, 16);
        }
        cp_commit();
    };

    load_chunk(0, 0);

    for (int ch = 0; ch < 4; ch++) {
        int st = ch & 1;
        if (ch < 3) {
            load_chunk(ch + 1, st ^ 1);
            cp_wait<1>();
        } else {
            cp_wait<0>();
        }
        __syncthreads();

        const __half* Ast = As + st * ASTG;
        const __half* Bst = Bs + st * BSTG;
        #pragma unroll
        for (int ks = 0; ks < 4; ks++) {
            int kb = ks * 16;
            unsigned a[2][4], b[4][2];
            #pragma unroll
            for (int mt = 0; mt < 2; mt++) {
                int r = wm + mt * 16 + g;
                a[mt][0] = *reinterpret_cast<const unsigned*>(&Ast[r * 72 + kb + 2 * t4]);
                a[mt][1] = *reinterpret_cast<const unsigned*>(&Ast[(r + 8) * 72 + kb + 2 * t4]);
                a[mt][2] = *reinterpret_cast<const unsigned*>(&Ast[r * 72 + kb + 2 * t4 + 8]);
                a[mt][3] = *reinterpret_cast<const unsigned*>(&Ast[(r + 8) * 72 + kb + 2 * t4 + 8]);
            }
            #pragma unroll
            for (int nt = 0; nt < 4; nt++) {
                int n = wn + nt * 8 + g;
                b[nt][0] = *reinterpret_cast<const unsigned*>(&Bst[n * 72 + kb + 2 * t4]);
                b[nt][1] = *reinterpret_cast<const unsigned*>(&Bst[n * 72 + kb + 2 * t4 + 8]);
            }
            #pragma unroll
            for (int mt = 0; mt < 2; mt++)
                #pragma unroll
                for (int nt = 0; nt < 4; nt++)
                    mma_f16(acc[mt][nt], a[mt], b[nt]);
        }
        __syncthreads();
    }

    // epilogue
    #pragma unroll
    for (int mt = 0; mt < 2; mt++) {
        #pragma unroll
        for (int half = 0; half < 2; half++) {
            int row = m0 + wm + mt * 16 + g + half * 8;
            if (row >= M) continue;
            #pragma unroll
            for (int nt = 0; nt < 4; nt++) {
                int col = n0 + wn + nt * 8 + 2 * t4;
                float v0 = acc[mt][nt][half * 2 + 0];
                float v1 = acc[mt][nt][half * 2 + 1];
                if (EPI) {
                    v0 += bias[col];
                    v1 += bias[col + 1];
                    if (EPI == 1) {
                        v0 = fmaxf(v0, 0.f);
                        v1 = fmaxf(v1, 0.f);
                    }
                }
                if (C16) {
                    *reinterpret_cast<__half2*>(&Ch[(size_t)row * NC + col]) =
                        __floats2half2_rn(v0, v1);
                } else {
                    *reinterpret_cast<float2*>(&C[(size_t)row * NC + col]) =
                        make_float2(v0, v1);
                }
            }
        }
    }
}

// ---------------- attention logits -----------------------------------------
__global__ void al_kernel(const float* __restrict__ asrc,
                          const float* __restrict__ adst,
                          int sel, int n, int H) {
    int t = blockIdx.x * blockDim.x + threadIdx.x;
    if (t >= n * H) return;
    const float* xp = sel ? g_xp2 : g_xp1;
    float* als = sel ? g_als2 : g_als1;
    float* ald = sel ? g_ald2 : g_ald1;
    int h = t % H;
    const float4* xr = reinterpret_cast<const float4*>(xp + (size_t)t * 64);
    const float4* a4 = reinterpret_cast<const float4*>(asrc + h * 64);
    const float4* d4 = reinterpret_cast<const float4*>(adst + h * 64);
    float s1 = 0.f, s2 = 0.f;
    #pragma unroll
    for (int q = 0; q < 16; q++) {
        float4 x = xr[q], a = a4[q], d = d4[q];
        s1 += x.x * a.x + x.y * a.y + x.z * a.z + x.w * a.w;
        s2 += x.x * d.x + x.y * d.y + x.z * d.z + x.w * d.w;
    }
    als[t] = s1;
    ald[t] = s2;
}

// ---------------- layer1 aggregation: one warp per node, all 4 heads -------
__global__ void agg1_kernel(const float* __restrict__ b1, int n) {
    int node = blockIdx.x * 8 + (threadIdx.x >> 5);
    if (node >= n) return;
    int lane = threadIdx.x & 31;
    int h = lane >> 3;
    int beg = g_offs[node], end = g_offs[node + 1];
    float adn = g_ald1[node * 4 + h];
    float m = -1e30f, ssum = 0.f;
    float acc[8];
    #pragma unroll
    for (int q = 0; q < 8; q++) acc[q] = 0.f;

    for (int j = beg; j < end; j++) {
        int s = g_ssrc[j];
        float a = g_als1[s * 4 + h] + adn;
        a = (a > 0.f) ? a : 0.2f * a;
        if (a > m) {
            float sc = __expf(m - a);
            ssum *= sc;
            #pragma unroll
            for (int q = 0; q < 8; q++) acc[q] *= sc;
            m = a;
        }
        float w = __expf(a - m);
        ssum += w;
        const float4* row = reinterpret_cast<const float4*>(
            &g_xp1[(size_t)s * 256 + lane * 8]);
        float4 v0 = row[0], v1 = row[1];
        acc[0] = fmaf(w, v0.x, acc[0]);
        acc[1] = fmaf(w, v0.y, acc[1]);
        acc[2] = fmaf(w, v0.z, acc[2]);
        acc[3] = fmaf(w, v0.w, acc[3]);
        acc[4] = fmaf(w, v1.x, acc[4]);
        acc[5] = fmaf(w, v1.y, acc[5]);
        acc[6] = fmaf(w, v1.z, acc[6]);
        acc[7] = fmaf(w, v1.w, acc[7]);
    }
    float inv = 1.f / ssum;
    int col = lane * 8;
    float o[8];
    #pragma unroll
    for (int q = 0; q < 8; q++) {
        float x = acc[q] * inv + b1[col + q];
        o[q] = (x > 0.f) ? x : expm1f(x);   // elu
    }
    __half2 p0 = __floats2half2_rn(o[0], o[1]);
    __half2 p1 = __floats2half2_rn(o[2], o[3]);
    __half2 p2 = __floats2half2_rn(o[4], o[5]);
    __half2 p3 = __floats2half2_rn(o[6], o[7]);
    __half2* dst = reinterpret_cast<__half2*>(&g_h16[(size_t)node * 256 + col]);
    dst[0] = p0; dst[1] = p1; dst[2] = p2; dst[3] = p3;
}

// ---------------- layer2 aggregation ---------------------------------------
__global__ void agg2_kernel(const float* __restrict__ b2,
                            float* __restrict__ out, int n) {
    int node = blockIdx.x * 8 + (threadIdx.x >> 5);
    if (node >= n) return;
    int lane = threadIdx.x & 31;
    int beg = g_offs[node], end = g_offs[node + 1];
    float adn = g_ald2[node];
    float m = -1e30f, ssum = 0.f, ax = 0.f, ay = 0.f;
    for (int j = beg; j < end; j++) {
        int s = g_ssrc[j];
        float a = g_als2[s] + adn;
        a = (a > 0.f) ? a : 0.2f * a;
        if (a > m) {
            float sc = __expf(m - a);
            ax *= sc; ay *= sc; ssum *= sc; m = a;
        }
        float w = __expf(a - m);
        ssum += w;
        float2 v = *reinterpret_cast<const float2*>(&g_xp2[(size_t)s * 64 + lane * 2]);
        ax = fmaf(w, v.x, ax);
        ay = fmaf(w, v.y, ay);
    }
    float inv = 1.f / ssum;
    int col = lane * 2;
    out[(size_t)node * 64 + col] =
        ax * inv + b2[col] + g_skip[(size_t)node * 64 + col];
    out[(size_t)node * 64 + col + 1] =
        ay * inv + b2[col + 1] + g_skip[(size_t)node * 64 + col + 1];
}

// ---------------- launch ---------------------------------------------------
extern "C" void kernel_launch(void* const* d_in, const int* in_sizes, int n_in,
                              void* d_out, int out_size) {
    const float* x_clean  = (const float*)d_in[0];
    const float* x_noised = (const float*)d_in[1];
    const int*   esrc     = (const int*)d_in[2];
    const int*   edst     = (const int*)d_in[3];
    const float* W1  = (const float*)d_in[4];
    const float* as1 = (const float*)d_in[5];
    const float* ad1 = (const float*)d_in[6];
    const float* b1  = (const float*)d_in[7];
    const float* W2  = (const float*)d_in[8];
    const float* as2 = (const float*)d_in[9];
    const float* ad2 = (const float*)d_in[10];
    const float* b2  = (const float*)d_in[11];
    float* out = (float*)d_out;

    int N = in_sizes[0] / 256;  // 50000
    int E = in_sizes[2];        // 800000

    const int SMB = (2 * 128 * 72 + 2 * 64 * 72) * 2;  // 55296 B
    cudaFuncSetAttribute(gemm_f16<0, false>, cudaFuncAttributeMaxDynamicSharedMemorySize, SMB);
    cudaFuncSetAttribute(gemm_f16<1, true>,  cudaFuncAttributeMaxDynamicSharedMemorySize, SMB);
    cudaFuncSetAttribute(gemm_f16<2, false>, cudaFuncAttributeMaxDynamicSharedMemorySize, SMB);

    int nb = (N + 255) / 256;       // 196
    int mtiles = (N + 127) / 128;   // 391

    // Launch order: profiler samples the 4th launch -> make it the hot GEMM.
    cvt_kernel<<<(NN * 256 / 4 + 255) / 256, 256>>>(x_noised, x_clean, W1, W2);  // 1
    init_deg_kernel<<<nb, 256>>>(N);                                             // 2
    count_kernel<<<(E + 255) / 256, 256>>>(edst, E);                             // 3
    gemm_f16<0, false><<<dim3(mtiles, 4), 256, SMB>>>(0, 0, nullptr, 1, N, 256); // 4: xp1 (profiled)
    gemm_f16<1, true><<<dim3(mtiles, 4), 256, SMB>>>(1, 0, b1, 2, N, 256);       // 5: hs16
    gemm_f16<2, false><<<dim3(mtiles, 1), 256, SMB>>>(2, 1, b2, 3, N, 64);       // 6: skip
    scan_local_kernel<<<nb, 256>>>(N);
    scan_bsum_kernel<<<1, 256>>>(nb, N);
    scan_add_kernel<<<nb, 256>>>(N);
    place_kernel<<<nb, 256>>>(N);
    scatter_kernel<<<(E + 255) / 256, 256>>>(esrc, edst, E);

    // layer 1 attention
    al_kernel<<<(N * 4 + 255) / 256, 256>>>(as1, ad1, 0, N, 4);
    agg1_kernel<<<(N + 7) / 8, 256>>>(b1, N);

    // layer 2
    gemm_f16<0, false><<<dim3(mtiles, 1), 256, SMB>>>(3, 1, nullptr, 4, N, 64);  // xp2
    al_kernel<<<(N + 255) / 256, 256>>>(as2, ad2, 1, N, 1);
    agg2_kernel<<<(N + 7) / 8, 256>>>(b2, out, N);
}

// round 6
// speedup vs baseline: 2.5820x; 1.0598x over previous
#include <cuda_runtime.h>
#include <cuda_fp16.h>
#include <cstdint>
#include <cstddef>

#define NN 50000
#define EE 800000
#define ET (EE + NN)

// ---------------- scratch (device globals; no allocation allowed) ----------
__device__ __align__(16) __half g_xp1h[(size_t)NN * 256];  // x_noised @ W1 (fp16)
__device__ __align__(16) __half g_xp2h[(size_t)NN * 64];   // h @ W2 (fp16)
__device__ __align__(16) float  g_skip[(size_t)NN * 64];
__device__ __align__(16) __half g_xa16[(size_t)NN * 256];  // fp16 x_noised
__device__ __align__(16) __half g_xc16[(size_t)NN * 256];  // fp16 x_clean
__device__ __align__(16) __half g_h16[(size_t)NN * 256];   // fp16 elu(layer1)
__device__ __align__(16) __half g_hs16[(size_t)NN * 256];  // fp16 relu(x_clean@W1+b1)
__device__ __align__(16) __half g_w1t16[256 * 256];        // W1^T fp16 [n][k]
__device__ __align__(16) __half g_w2t16[64 * 256];         // W2^T fp16 [n][k]
__device__ __align__(16) float g_als1[NN * 4];
__device__ __align__(16) float g_ald1[NN * 4];
__device__ __align__(16) float g_als2[NN];
__device__ __align__(16) float g_ald2[NN];
__device__ int g_deg[NN];
__device__ int g_offs[NN + 1];
__device__ int g_cur[NN];
__device__ int g_ssrc[ET];
__device__ int g_bsum[256];
__device__ int g_bpre[256];

// ---------------- fp16 conversion + weight transpose -----------------------
__global__ void cvt_kernel(const float* __restrict__ xn,
                           const float* __restrict__ xc,
                           const float* __restrict__ W1,
                           const float* __restrict__ W2) {
    int i = blockIdx.x * 256 + threadIdx.x;
    if (i < (NN * 256) / 4) {
        float4 a = reinterpret_cast<const float4*>(xn)[i];
        float4 b = reinterpret_cast<const float4*>(xc)[i];
        reinterpret_cast<__half2*>(g_xa16)[i * 2]     = __floats2half2_rn(a.x, a.y);
        reinterpret_cast<__half2*>(g_xa16)[i * 2 + 1] = __floats2half2_rn(a.z, a.w);
        reinterpret_cast<__half2*>(g_xc16)[i * 2]     = __floats2half2_rn(b.x, b.y);
        reinterpret_cast<__half2*>(g_xc16)[i * 2 + 1] = __floats2half2_rn(b.z, b.w);
    }
    if (i < 256 * 256) {
        int k = i >> 8, n = i & 255;
        g_w1t16[n * 256 + k] = __float2half_rn(W1[k * 256 + n]);
    }
    if (i < 256 * 64) {
        int k = i >> 6, n = i & 63;
        g_w2t16[n * 256 + k] = __float2half_rn(W2[k * 64 + n]);
    }
}

// ---------------- CSR build ------------------------------------------------
__global__ void init_deg_kernel(int n) {
    int i = blockIdx.x * blockDim.x + threadIdx.x;
    if (i < n) g_deg[i] = 1;
}

__global__ void count_kernel(const int* __restrict__ edst, int e) {
    int i = blockIdx.x * blockDim.x + threadIdx.x;
    if (i < e) atomicAdd(&g_deg[edst[i]], 1);
}

__global__ void scan_local_kernel(int n) {
    __shared__ int ws[9];
    int tid = threadIdx.x, lane = tid & 31, w = tid >> 5;
    int i = blockIdx.x * 256 + tid;
    int v = (i < n) ? g_deg[i] : 0;
    int x = v;
    #pragma unroll
    for (int o = 1; o < 32; o <<= 1) {
        int y = __shfl_up_sync(0xffffffffu, x, o);
        if (lane >= o) x += y;
    }
    if (lane == 31) ws[w] = x;
    __syncthreads();
    if (tid == 0) {
        int s = 0;
        #pragma unroll
        for (int q = 0; q < 8; q++) { int t = ws[q]; ws[q] = s; s += t; }
        g_bsum[blockIdx.x] = s;
    }
    __syncthreads();
    if (i < n) g_offs[i] = ws[w] + x - v;
}

__global__ void scan_bsum_kernel(int nb, int n) {
    __shared__ int wtot[8];
    int tid = threadIdx.x, lane = tid & 31, w = tid >> 5;
    int v = (tid < nb) ? g_bsum[tid] : 0;
    int x = v;
    #pragma unroll
    for (int o = 1; o < 32; o <<= 1) {
        int y = __shfl_up_sync(0xffffffffu, x, o);
        if (lane >= o) x += y;
    }
    if (lane == 31) wtot[w] = x;
    __syncthreads();
    int pre = 0;
    #pragma unroll
    for (int q = 0; q < 8; q++) pre += (q < w) ? wtot[q] : 0;
    if (tid < nb) g_bpre[tid] = pre + x - v;
    if (tid == nb - 1) g_offs[n] = pre + x;
}

__global__ void scan_add_kernel(int n) {
    int i = blockIdx.x * 256 + threadIdx.x;
    if (i < n && blockIdx.x > 0) g_offs[i] += g_bpre[blockIdx.x];
}

__global__ void place_kernel(int n) {
    int i = blockIdx.x * blockDim.x + threadIdx.x;
    if (i < n) {
        int o = g_offs[i];
        g_ssrc[o] = i;
        g_cur[i] = o + 1;
    }
}

__global__ void scatter_kernel(const int* __restrict__ esrc,
                               const int* __restrict__ edst, int e) {
    int i = blockIdx.x * blockDim.x + threadIdx.x;
    if (i < e) {
        int d = edst[i];
        int pos = atomicAdd(&g_cur[d], 1);
        g_ssrc[pos] = esrc[i];
    }
}

// ---------------- FP16 tensor-core GEMM, cp.async + ldmatrix ---------------
__device__ __forceinline__ uint32_t smem_u32(const void* p) {
    uint32_t a;
    asm("{ .reg .u64 t; cvta.to.shared.u64 t, %1; cvt.u32.u64 %0, t; }"
        : "=r"(a) : "l"(p));
    return a;
}
__device__ __forceinline__ void cp16(uint32_t dst, const void* src, int srcsz) {
    asm volatile("cp.async.cg.shared.global [%0], [%1], 16, %2;"
                 :: "r"(dst), "l"(src), "r"(srcsz));
}
__device__ __forceinline__ void cp_commit() {
    asm volatile("cp.async.commit_group;");
}
template <int N>
__device__ __forceinline__ void cp_wait() {
    asm volatile("cp.async.wait_group %0;" :: "n"(N));
}
__device__ __forceinline__ void ldsm_x4(unsigned& r0, unsigned& r1,
                                        unsigned& r2, unsigned& r3, uint32_t a) {
    asm volatile("ldmatrix.sync.aligned.m8n8.x4.shared.b16 {%0,%1,%2,%3}, [%4];"
                 : "=r"(r0), "=r"(r1), "=r"(r2), "=r"(r3) : "r"(a));
}
__device__ __forceinline__ void mma_f16(float* c, const unsigned* a,
                                        const unsigned* b) {
    asm volatile(
        "mma.sync.aligned.m16n8k16.row.col.f32.f16.f16.f32 "
        "{%0,%1,%2,%3}, {%4,%5,%6,%7}, {%8,%9}, {%0,%1,%2,%3};\n"
        : "+f"(c[0]), "+f"(c[1]), "+f"(c[2]), "+f"(c[3])
        : "r"(a[0]), "r"(a[1]), "r"(a[2]), "r"(a[3]), "r"(b[0]), "r"(b[1]));
}

// C[M,NC] = A16[M,256] @ B16t[NC,256]^T. Tile 128x64x64, 8 warps, 2 stages.
// EPI: 0 none, 1 +bias relu, 2 +bias. C16: write fp16 else fp32.
template <int EPI, bool C16>
__global__ void __launch_bounds__(256) gemm_f16(
    int asel, int bsel, const float* __restrict__ bias, int csel, int M, int NC) {
    const __half* A = (asel == 0) ? g_xa16
                    : (asel == 1) ? g_xc16
                    : (asel == 2) ? g_hs16
                                  : g_h16;
    const __half* Bt = bsel ? g_w2t16 : g_w1t16;
    __half* Ch = (csel == 1) ? g_xp1h : (csel == 2) ? g_hs16 : g_xp2h;
    float* Cf = g_skip;

    // smem (halfs): As[2][128][72], Bs[2][64][72]
    extern __shared__ __half dynsm[];
    __half* As = dynsm;
    __half* Bs = dynsm + 2 * 128 * 72;
    const int ASTG = 128 * 72, BSTG = 64 * 72;

    int tid = threadIdx.x;
    int wid = tid >> 5, lane = tid & 31;
    int g = lane >> 2, t4 = lane & 3;
    int wm = (wid >> 1) * 32;
    int wn = (wid & 1) * 32;
    int m0 = blockIdx.x * 128;
    int n0 = blockIdx.y * 64;

    uint32_t aA = smem_u32(As), aB = smem_u32(Bs);

    // ldmatrix lane address offsets
    int a_row_off = (lane & 7) + ((lane >> 3) & 1) * 8;  // within 16-row tile
    int a_col_off = ((lane >> 4) & 1) * 8;               // k offset 0 or 8
    int b_row_off = (lane & 7) + ((lane >> 4) & 1) * 8;  // within 16-n group
    int b_col_off = ((lane >> 3) & 1) * 8;

    float acc[2][4][4];
    #pragma unroll
    for (int mt = 0; mt < 2; mt++)
        #pragma unroll
        for (int nt = 0; nt < 4; nt++)
            #pragma unroll
            for (int q = 0; q < 4; q++) acc[mt][nt][q] = 0.f;

    auto load_chunk = [&](int ch, int st) {
        int k0 = ch * 64;
        #pragma unroll
        for (int i = 0; i < 4; i++) {
            int lin = tid + i * 256;
            int row = lin >> 3, seg = lin & 7;
            uint32_t dst = aA + (uint32_t)(st * ASTG + row * 72 + seg * 8) * 2u;
            const __half* src = &A[(size_t)(m0 + row) * 256 + k0 + seg * 8];
            cp16(dst, src, (m0 + row < M) ? 16 : 0);
        }
        #pragma unroll
        for (int i = 0; i < 2; i++) {
            int lin = tid + i * 256;
            int row = lin >> 3, seg = lin & 7;
            uint32_t dst = aB + (uint32_t)(st * BSTG + row * 72 + seg * 8) * 2u;
            const __half* src = &Bt[(size_t)(n0 + row) * 256 + k0 + seg * 8];
            cp16(dst, src, 16);
        }
        cp_commit();
    };

    load_chunk(0, 0);

    for (int ch = 0; ch < 4; ch++) {
        int st = ch & 1;
        if (ch < 3) {
            load_chunk(ch + 1, st ^ 1);
            cp_wait<1>();
        } else {
            cp_wait<0>();
        }
        __syncthreads();

        uint32_t baseA = aA + (uint32_t)(st * ASTG) * 2u;
        uint32_t baseB = aB + (uint32_t)(st * BSTG) * 2u;
        #pragma unroll
        for (int ks = 0; ks < 4; ks++) {
            int kb = ks * 16;
            unsigned a[2][4], b[4][2];
            #pragma unroll
            for (int mt = 0; mt < 2; mt++) {
                uint32_t ad = baseA +
                    (uint32_t)((wm + mt * 16 + a_row_off) * 72 + kb + a_col_off) * 2u;
                ldsm_x4(a[mt][0], a[mt][1], a[mt][2], a[mt][3], ad);
            }
            #pragma unroll
            for (int p = 0; p < 2; p++) {
                uint32_t bd = baseB +
                    (uint32_t)((wn + p * 16 + b_row_off) * 72 + kb + b_col_off) * 2u;
                ldsm_x4(b[2 * p][0], b[2 * p][1], b[2 * p + 1][0], b[2 * p + 1][1], bd);
            }
            #pragma unroll
            for (int mt = 0; mt < 2; mt++)
                #pragma unroll
                for (int nt = 0; nt < 4; nt++)
                    mma_f16(acc[mt][nt], a[mt], b[nt]);
        }
        __syncthreads();
    }

    // epilogue
    #pragma unroll
    for (int mt = 0; mt < 2; mt++) {
        #pragma unroll
        for (int half = 0; half < 2; half++) {
            int row = m0 + wm + mt * 16 + g + half * 8;
            if (row >= M) continue;
            #pragma unroll
            for (int nt = 0; nt < 4; nt++) {
                int col = n0 + wn + nt * 8 + 2 * t4;
                float v0 = acc[mt][nt][half * 2 + 0];
                float v1 = acc[mt][nt][half * 2 + 1];
                if (EPI) {
                    v0 += bias[col];
                    v1 += bias[col + 1];
                    if (EPI == 1) {
                        v0 = fmaxf(v0, 0.f);
                        v1 = fmaxf(v1, 0.f);
                    }
                }
                if (C16) {
                    *reinterpret_cast<__half2*>(&Ch[(size_t)row * NC + col]) =
                        __floats2half2_rn(v0, v1);
                } else {
                    *reinterpret_cast<float2*>(&Cf[(size_t)row * NC + col]) =
                        make_float2(v0, v1);
                }
            }
        }
    }
}

// ---------------- attention logits (fp16 xp) --------------------------------
__global__ void al_kernel(const float* __restrict__ asrc,
                          const float* __restrict__ adst,
                          int sel, int n, int H) {
    int t = blockIdx.x * blockDim.x + threadIdx.x;
    if (t >= n * H) return;
    const __half* xp = sel ? g_xp2h : g_xp1h;
    float* als = sel ? g_als2 : g_als1;
    float* ald = sel ? g_ald2 : g_ald1;
    int h = t % H;
    const __half2* xr = reinterpret_cast<const __half2*>(xp + (size_t)t * 64);
    const float2* a2 = reinterpret_cast<const float2*>(asrc + h * 64);
    const float2* d2 = reinterpret_cast<const float2*>(adst + h * 64);
    float s1 = 0.f, s2 = 0.f;
    #pragma unroll
    for (int q = 0; q < 32; q++) {
        float2 x = __half22float2(xr[q]);
        float2 a = a2[q], d = d2[q];
        s1 += x.x * a.x + x.y * a.y;
        s2 += x.x * d.x + x.y * d.y;
    }
    als[t] = s1;
    ald[t] = s2;
}

// ---------------- layer1 aggregation: one warp per node, all 4 heads -------
__global__ void agg1_kernel(const float* __restrict__ b1, int n) {
    int node = blockIdx.x * 8 + (threadIdx.x >> 5);
    if (node >= n) return;
    int lane = threadIdx.x & 31;
    int h = lane >> 3;
    int beg = g_offs[node], end = g_offs[node + 1];
    float adn = g_ald1[node * 4 + h];
    float m = -1e30f, ssum = 0.f;
    float acc[8];
    #pragma unroll
    for (int q = 0; q < 8; q++) acc[q] = 0.f;

    for (int j = beg; j < end; j++) {
        int s = g_ssrc[j];
        float a = g_als1[s * 4 + h] + adn;
        a = (a > 0.f) ? a : 0.2f * a;
        if (a > m) {
            float sc = __expf(m - a);
            ssum *= sc;
            #pragma unroll
            for (int q = 0; q < 8; q++) acc[q] *= sc;
            m = a;
        }
        float w = __expf(a - m);
        ssum += w;
        uint4 u = *reinterpret_cast<const uint4*>(
            &g_xp1h[(size_t)s * 256 + lane * 8]);   // 8 halfs = 16B
        float2 f0 = __half22float2(*reinterpret_cast<__half2*>(&u.x));
        float2 f1 = __half22float2(*reinterpret_cast<__half2*>(&u.y));
        float2 f2 = __half22float2(*reinterpret_cast<__half2*>(&u.z));
        float2 f3 = __half22float2(*reinterpret_cast<__half2*>(&u.w));
        acc[0] = fmaf(w, f0.x, acc[0]);
        acc[1] = fmaf(w, f0.y, acc[1]);
        acc[2] = fmaf(w, f1.x, acc[2]);
        acc[3] = fmaf(w, f1.y, acc[3]);
        acc[4] = fmaf(w, f2.x, acc[4]);
        acc[5] = fmaf(w, f2.y, acc[5]);
        acc[6] = fmaf(w, f3.x, acc[6]);
        acc[7] = fmaf(w, f3.y, acc[7]);
    }
    float inv = 1.f / ssum;
    int col = lane * 8;
    float o[8];
    #pragma unroll
    for (int q = 0; q < 8; q++) {
        float x = acc[q] * inv + b1[col + q];
        o[q] = (x > 0.f) ? x : expm1f(x);   // elu
    }
    __half2* dst = reinterpret_cast<__half2*>(&g_h16[(size_t)node * 256 + col]);
    dst[0] = __floats2half2_rn(o[0], o[1]);
    dst[1] = __floats2half2_rn(o[2], o[3]);
    dst[2] = __floats2half2_rn(o[4], o[5]);
    dst[3] = __floats2half2_rn(o[6], o[7]);
}

// ---------------- layer2 aggregation ---------------------------------------
__global__ void agg2_kernel(const float* __restrict__ b2,
                            float* __restrict__ out, int n) {
    int node = blockIdx.x * 8 + (threadIdx.x >> 5);
    if (node >= n) return;
    int lane = threadIdx.x & 31;
    int beg = g_offs[node], end = g_offs[node + 1];
    float adn = g_ald2[node];
    float m = -1e30f, ssum = 0.f, ax = 0.f, ay = 0.f;
    for (int j = beg; j < end; j++) {
        int s = g_ssrc[j];
        float a = g_als2[s] + adn;
        a = (a > 0.f) ? a : 0.2f * a;
        if (a > m) {
            float sc = __expf(m - a);
            ax *= sc; ay *= sc; ssum *= sc; m = a;
        }
        float w = __expf(a - m);
        ssum += w;
        float2 v = __half22float2(*reinterpret_cast<const __half2*>(
            &g_xp2h[(size_t)s * 64 + lane * 2]));
        ax = fmaf(w, v.x, ax);
        ay = fmaf(w, v.y, ay);
    }
    float inv = 1.f / ssum;
    int col = lane * 2;
    out[(size_t)node * 64 + col] =
        ax * inv + b2[col] + g_skip[(size_t)node * 64 + col];
    out[(size_t)node * 64 + col + 1] =
        ay * inv + b2[col + 1] + g_skip[(size_t)node * 64 + col + 1];
}

// ---------------- launch ---------------------------------------------------
extern "C" void kernel_launch(void* const* d_in, const int* in_sizes, int n_in,
                              void* d_out, int out_size) {
    const float* x_clean  = (const float*)d_in[0];
    const float* x_noised = (const float*)d_in[1];
    const int*   esrc     = (const int*)d_in[2];
    const int*   edst     = (const int*)d_in[3];
    const float* W1  = (const float*)d_in[4];
    const float* as1 = (const float*)d_in[5];
    const float* ad1 = (const float*)d_in[6];
    const float* b1  = (const float*)d_in[7];
    const float* W2  = (const float*)d_in[8];
    const float* as2 = (const float*)d_in[9];
    const float* ad2 = (const float*)d_in[10];
    const float* b2  = (const float*)d_in[11];
    float* out = (float*)d_out;

    int N = in_sizes[0] / 256;  // 50000
    int E = in_sizes[2];        // 800000

    const int SMB = (2 * 128 * 72 + 2 * 64 * 72) * 2;  // 55296 B
    cudaFuncSetAttribute(gemm_f16<0, true>,  cudaFuncAttributeMaxDynamicSharedMemorySize, SMB);
    cudaFuncSetAttribute(gemm_f16<1, true>,  cudaFuncAttributeMaxDynamicSharedMemorySize, SMB);
    cudaFuncSetAttribute(gemm_f16<2, false>, cudaFuncAttributeMaxDynamicSharedMemorySize, SMB);

    int nb = (N + 255) / 256;       // 196
    int mtiles = (N + 127) / 128;   // 391

    // Launch order: profiler samples the 4th launch -> hot GEMM there.
    cvt_kernel<<<(NN * 256 / 4 + 255) / 256, 256>>>(x_noised, x_clean, W1, W2);  // 1
    init_deg_kernel<<<nb, 256>>>(N);                                             // 2
    count_kernel<<<(E + 255) / 256, 256>>>(edst, E);                             // 3
    gemm_f16<0, true><<<dim3(mtiles, 4), 256, SMB>>>(0, 0, nullptr, 1, N, 256);  // 4: xp1 (profiled)
    gemm_f16<1, true><<<dim3(mtiles, 4), 256, SMB>>>(1, 0, b1, 2, N, 256);       // 5: hs16
    gemm_f16<2, false><<<dim3(mtiles, 1), 256, SMB>>>(2, 1, b2, 3, N, 64);       // 6: skip
    scan_local_kernel<<<nb, 256>>>(N);
    scan_bsum_kernel<<<1, 256>>>(nb, N);
    scan_add_kernel<<<nb, 256>>>(N);
    place_kernel<<<nb, 256>>>(N);
    scatter_kernel<<<(E + 255) / 256, 256>>>(esrc, edst, E);

    // layer 1 attention
    al_kernel<<<(N * 4 + 255) / 256, 256>>>(as1, ad1, 0, N, 4);
    agg1_kernel<<<(N + 7) / 8, 256>>>(b1, N);

    // layer 2
    gemm_f16<0, true><<<dim3(mtiles, 1), 256, SMB>>>(3, 1, nullptr, 4, N, 64);   // xp2
    al_kernel<<<(N + 255) / 256, 256>>>(as2, ad2, 1, N, 1);
    agg2_kernel<<<(N + 7) / 8, 256>>>(b2, out, N);
}

// round 7
// speedup vs baseline: 2.6951x; 1.0438x over previous
#include <cuda_runtime.h>
#include <cuda_fp16.h>
#include <cstdint>
#include <cstddef>

#define NN 50000
#define EE 800000
#define ET (EE + NN)

// ---------------- scratch (device globals; no allocation allowed) ----------
__device__ __align__(16) __half g_xp1h[(size_t)NN * 256];  // x_noised @ W1 (fp16)
__device__ __align__(16) __half g_xp2h[(size_t)NN * 64];   // h @ W2 (fp16)
__device__ __align__(16) float  g_skip[(size_t)NN * 64];
__device__ __align__(16) __half g_xa16[(size_t)NN * 256];  // fp16 x_noised
__device__ __align__(16) __half g_xc16[(size_t)NN * 256];  // fp16 x_clean
__device__ __align__(16) __half g_h16[(size_t)NN * 256];   // fp16 elu(layer1)
__device__ __align__(16) __half g_hs16[(size_t)NN * 256];  // fp16 relu(x_clean@W1+b1)
__device__ __align__(16) __half g_w1t16[320 * 256];        // W1^T fp16 [n][k] + 8 aug logit rows
__device__ __align__(16) __half g_w2t16[128 * 256];        // W2^T fp16 [n][k] + 2 aug logit rows
__device__ __align__(16) float g_als1[(size_t)NN * 4];
__device__ __align__(16) float g_ald1[(size_t)NN * 4];
__device__ __align__(16) float g_als2[NN];
__device__ __align__(16) float g_ald2[NN];
__device__ int g_deg[NN];
__device__ int g_offs[NN + 1];
__device__ int g_cur[NN];
__device__ int g_ssrc[ET];
__device__ int g_bsum[256];
__device__ int g_bpre[256];

// ------- fp16 conversion + weight transpose + augmented logit columns ------
__global__ void cvt_kernel(const float* __restrict__ xn,
                           const float* __restrict__ xc,
                           const float* __restrict__ W1,
                           const float* __restrict__ W2,
                           const float* __restrict__ as1,
                           const float* __restrict__ ad1,
                           const float* __restrict__ as2,
                           const float* __restrict__ ad2) {
    int i = blockIdx.x * 256 + threadIdx.x;
    if (i < (NN * 256) / 4) {
        float4 a = reinterpret_cast<const float4*>(xn)[i];
        float4 b = reinterpret_cast<const float4*>(xc)[i];
        reinterpret_cast<__half2*>(g_xa16)[i * 2]     = __floats2half2_rn(a.x, a.y);
        reinterpret_cast<__half2*>(g_xa16)[i * 2 + 1] = __floats2half2_rn(a.z, a.w);
        reinterpret_cast<__half2*>(g_xc16)[i * 2]     = __floats2half2_rn(b.x, b.y);
        reinterpret_cast<__half2*>(g_xc16)[i * 2 + 1] = __floats2half2_rn(b.z, b.w);
    }
    if (i < NN) g_deg[i] = 1;  // self-loop (init_deg fused)
    if (i < 256 * 256) {
        int k = i >> 8, n = i & 255;
        g_w1t16[n * 256 + k] = __float2half_rn(W1[k * 256 + n]);
    }
    if (i < 256 * 64) {
        int k = i >> 6, n = i & 63;
        g_w2t16[n * 256 + k] = __float2half_rn(W2[k * 64 + n]);
    }
    // augmented layer1 logit columns: w~[k, j] = sum_c W1[k, h*64+c]*a[h*64+c]
    if (i < 256 * 8) {
        int k = i >> 3, j = i & 7;
        int h = j & 3;
        const float* av = (j < 4) ? as1 : ad1;
        float s = 0.f;
        #pragma unroll 8
        for (int c = 0; c < 64; c++)
            s += W1[k * 256 + h * 64 + c] * av[h * 64 + c];
        g_w1t16[(256 + j) * 256 + k] = __float2half_rn(s);
    }
    // augmented layer2 logit columns
    if (i < 256 * 2) {
        int k = i >> 1, j = i & 1;
        const float* av = j ? ad2 : as2;
        float s = 0.f;
        #pragma unroll 8
        for (int c = 0; c < 64; c++)
            s += W2[k * 64 + c] * av[c];
        g_w2t16[(64 + j) * 256 + k] = __float2half_rn(s);
    }
}

// ---------------- CSR build ------------------------------------------------
__global__ void count_kernel(const int* __restrict__ edst, int e) {
    int i = blockIdx.x * blockDim.x + threadIdx.x;
    if (i < e) atomicAdd(&g_deg[edst[i]], 1);
}

__global__ void scan_local_kernel(int n) {
    __shared__ int ws[9];
    int tid = threadIdx.x, lane = tid & 31, w = tid >> 5;
    int i = blockIdx.x * 256 + tid;
    int v = (i < n) ? g_deg[i] : 0;
    int x = v;
    #pragma unroll
    for (int o = 1; o < 32; o <<= 1) {
        int y = __shfl_up_sync(0xffffffffu, x, o);
        if (lane >= o) x += y;
    }
    if (lane == 31) ws[w] = x;
    __syncthreads();
    if (tid == 0) {
        int s = 0;
        #pragma unroll
        for (int q = 0; q < 8; q++) { int t = ws[q]; ws[q] = s; s += t; }
        g_bsum[blockIdx.x] = s;
    }
    __syncthreads();
    if (i < n) g_offs[i] = ws[w] + x - v;
}

__global__ void scan_bsum_kernel(int nb, int n) {
    __shared__ int wtot[8];
    int tid = threadIdx.x, lane = tid & 31, w = tid >> 5;
    int v = (tid < nb) ? g_bsum[tid] : 0;
    int x = v;
    #pragma unroll
    for (int o = 1; o < 32; o <<= 1) {
        int y = __shfl_up_sync(0xffffffffu, x, o);
        if (lane >= o) x += y;
    }
    if (lane == 31) wtot[w] = x;
    __syncthreads();
    int pre = 0;
    #pragma unroll
    for (int q = 0; q < 8; q++) pre += (q < w) ? wtot[q] : 0;
    if (tid < nb) g_bpre[tid] = pre + x - v;
    if (tid == nb - 1) g_offs[n] = pre + x;
}

// scan_add + place fused
__global__ void scan_add_place_kernel(int n) {
    int i = blockIdx.x * 256 + threadIdx.x;
    if (i < n) {
        int o = g_offs[i] + (blockIdx.x > 0 ? g_bpre[blockIdx.x] : 0);
        g_offs[i] = o;
        g_ssrc[o] = i;       // self-loop first
        g_cur[i] = o + 1;
    }
}

__global__ void scatter_kernel(const int* __restrict__ esrc,
                               const int* __restrict__ edst, int e) {
    int i = blockIdx.x * blockDim.x + threadIdx.x;
    if (i < e) {
        int d = edst[i];
        int pos = atomicAdd(&g_cur[d], 1);
        g_ssrc[pos] = esrc[i];
    }
}

// ---------------- FP16 tensor-core GEMM, 3-stage cp.async + ldmatrix -------
__device__ __forceinline__ uint32_t smem_u32(const void* p) {
    uint32_t a;
    asm("{ .reg .u64 t; cvta.to.shared.u64 t, %1; cvt.u32.u64 %0, t; }"
        : "=r"(a) : "l"(p));
    return a;
}
__device__ __forceinline__ void cp16(uint32_t dst, const void* src, int srcsz) {
    asm volatile("cp.async.cg.shared.global [%0], [%1], 16, %2;"
                 :: "r"(dst), "l"(src), "r"(srcsz));
}
__device__ __forceinline__ void cp_commit() {
    asm volatile("cp.async.commit_group;");
}
template <int N>
__device__ __forceinline__ void cp_wait() {
    asm volatile("cp.async.wait_group %0;" :: "n"(N));
}
__device__ __forceinline__ void ldsm_x4(unsigned& r0, unsigned& r1,
                                        unsigned& r2, unsigned& r3, uint32_t a) {
    asm volatile("ldmatrix.sync.aligned.m8n8.x4.shared.b16 {%0,%1,%2,%3}, [%4];"
                 : "=r"(r0), "=r"(r1), "=r"(r2), "=r"(r3) : "r"(a));
}
__device__ __forceinline__ void mma_f16(float* c, const unsigned* a,
                                        const unsigned* b) {
    asm volatile(
        "mma.sync.aligned.m16n8k16.row.col.f32.f16.f16.f32 "
        "{%0,%1,%2,%3}, {%4,%5,%6,%7}, {%8,%9}, {%0,%1,%2,%3};\n"
        : "+f"(c[0]), "+f"(c[1]), "+f"(c[2]), "+f"(c[3])
        : "r"(a[0]), "r"(a[1]), "r"(a[2]), "r"(a[3]), "r"(b[0]), "r"(b[1]));
}

// C[M,NC] = A16[M,256] @ B16t[NC(+aug),256]^T. Tile 128x64x64, 8 warps, 3 stages.
// Tiles with n0 >= ncMain write attention logits instead (augsel 0=layer1, 1=layer2).
// EPI: 0 none, 1 +bias relu, 2 +bias. C16: write fp16 else fp32 (skip).
template <int EPI, bool C16>
__global__ void __launch_bounds__(256) gemm_f16(
    int asel, int bsel, const float* __restrict__ bias, int csel,
    int M, int NC, int augsel) {
    const __half* A = (asel == 0) ? g_xa16
                    : (asel == 1) ? g_xc16
                    : (asel == 2) ? g_hs16
                                  : g_h16;
    const __half* Bt = bsel ? g_w2t16 : g_w1t16;
    __half* Ch = (csel == 1) ? g_xp1h : (csel == 2) ? g_hs16 : g_xp2h;
    float* Cf = g_skip;

    // smem (halfs): As[3][128][72], Bs[3][64][72]
    extern __shared__ __half dynsm[];
    __half* As = dynsm;
    __half* Bs = dynsm + 3 * 128 * 72;
    const int ASTG = 128 * 72, BSTG = 64 * 72;

    int tid = threadIdx.x;
    int wid = tid >> 5, lane = tid & 31;
    int g = lane >> 2, t4 = lane & 3;
    int wm = (wid >> 1) * 32;
    int wn = (wid & 1) * 32;
    int m0 = blockIdx.x * 128;
    int n0 = blockIdx.y * 64;
    bool isAug = (n0 >= NC);

    uint32_t aA = smem_u32(As), aB = smem_u32(Bs);

    int a_row_off = (lane & 7) + ((lane >> 3) & 1) * 8;
    int a_col_off = ((lane >> 4) & 1) * 8;
    int b_row_off = (lane & 7) + ((lane >> 4) & 1) * 8;
    int b_col_off = ((lane >> 3) & 1) * 8;

    float acc[2][4][4];
    #pragma unroll
    for (int mt = 0; mt < 2; mt++)
        #pragma unroll
        for (int nt = 0; nt < 4; nt++)
            #pragma unroll
            for (int q = 0; q < 4; q++) acc[mt][nt][q] = 0.f;

    auto load_chunk = [&](int ch, int st) {
        int k0 = ch * 64;
        #pragma unroll
        for (int i = 0; i < 4; i++) {
            int lin = tid + i * 256;
            int row = lin >> 3, seg = lin & 7;
            uint32_t dst = aA + (uint32_t)(st * ASTG + row * 72 + seg * 8) * 2u;
            const __half* src = &A[(size_t)(m0 + row) * 256 + k0 + seg * 8];
            cp16(dst, src, (m0 + row < M) ? 16 : 0);
        }
        #pragma unroll
        for (int i = 0; i < 2; i++) {
            int lin = tid + i * 256;
            int row = lin >> 3, seg = lin & 7;
            uint32_t dst = aB + (uint32_t)(st * BSTG + row * 72 + seg * 8) * 2u;
            const __half* src = &Bt[(size_t)(n0 + row) * 256 + k0 + seg * 8];
            cp16(dst, src, 16);
        }
        cp_commit();
    };

    load_chunk(0, 0);
    load_chunk(1, 1);

    #pragma unroll
    for (int ch = 0; ch < 4; ch++) {
        if (ch < 3) cp_wait<1>(); else cp_wait<0>();
        __syncthreads();

        int st = ch % 3;
        uint32_t baseA = aA + (uint32_t)(st * ASTG) * 2u;
        uint32_t baseB = aB + (uint32_t)(st * BSTG) * 2u;
        #pragma unroll
        for (int ks = 0; ks < 4; ks++) {
            int kb = ks * 16;
            unsigned a[2][4], b[4][2];
            #pragma unroll
            for (int mt = 0; mt < 2; mt++) {
                uint32_t ad = baseA +
                    (uint32_t)((wm + mt * 16 + a_row_off) * 72 + kb + a_col_off) * 2u;
                ldsm_x4(a[mt][0], a[mt][1], a[mt][2], a[mt][3], ad);
            }
            #pragma unroll
            for (int p = 0; p < 2; p++) {
                uint32_t bd = baseB +
                    (uint32_t)((wn + p * 16 + b_row_off) * 72 + kb + b_col_off) * 2u;
                ldsm_x4(b[2 * p][0], b[2 * p][1], b[2 * p + 1][0], b[2 * p + 1][1], bd);
            }
            #pragma unroll
            for (int mt = 0; mt < 2; mt++)
                #pragma unroll
                for (int nt = 0; nt < 4; nt++)
                    mma_f16(acc[mt][nt], a[mt], b[nt]);
        }
        if (ch + 2 < 4) load_chunk(ch + 2, (ch + 2) % 3);
    }

    // epilogue
    #pragma unroll
    for (int mt = 0; mt < 2; mt++) {
        #pragma unroll
        for (int half = 0; half < 2; half++) {
            int row = m0 + wm + mt * 16 + g + half * 8;
            if (row >= M) continue;
            #pragma unroll
            for (int nt = 0; nt < 4; nt++) {
                int col = n0 + wn + nt * 8 + 2 * t4;
                float v0 = acc[mt][nt][half * 2 + 0];
                float v1 = acc[mt][nt][half * 2 + 1];
                if (isAug) {
                    int c = col - NC;   // even
                    if (c < 8) {
                        if (augsel == 0) {
                            // cols 0-3: als1 heads, 4-7: ald1 heads
                            if (c < 4) g_als1[(size_t)row * 4 + c] = v0;
                            else       g_ald1[(size_t)row * 4 + c - 4] = v0;
                            int c1 = c + 1;
                            if (c1 < 4) g_als1[(size_t)row * 4 + c1] = v1;
                            else        g_ald1[(size_t)row * 4 + c1 - 4] = v1;
                        } else {
                            if (c == 0) { g_als2[row] = v0; g_ald2[row] = v1; }
                        }
                    }
                    continue;
                }
                if (EPI) {
                    v0 += bias[col];
                    v1 += bias[col + 1];
                    if (EPI == 1) {
                        v0 = fmaxf(v0, 0.f);
                        v1 = fmaxf(v1, 0.f);
                    }
                }
                if (C16) {
                    *reinterpret_cast<__half2*>(&Ch[(size_t)row * NC + col]) =
                        __floats2half2_rn(v0, v1);
                } else {
                    *reinterpret_cast<float2*>(&Cf[(size_t)row * NC + col]) =
                        make_float2(v0, v1);
                }
            }
        }
    }
}

// ---------------- layer1 aggregation: one warp per node, all 4 heads -------
__global__ void agg1_kernel(const float* __restrict__ b1, int n) {
    int node = blockIdx.x * 8 + (threadIdx.x >> 5);
    if (node >= n) return;
    int lane = threadIdx.x & 31;
    int h = lane >> 3;
    int beg = g_offs[node], end = g_offs[node + 1];
    float adn = g_ald1[node * 4 + h];
    float m = -1e30f, ssum = 0.f;
    float acc[8];
    #pragma unroll
    for (int q = 0; q < 8; q++) acc[q] = 0.f;

    for (int j = beg; j < end; j++) {
        int s = g_ssrc[j];
        float a = g_als1[s * 4 + h] + adn;
        a = (a > 0.f) ? a : 0.2f * a;
        if (a > m) {
            float sc = __expf(m - a);
            ssum *= sc;
            #pragma unroll
            for (int q = 0; q < 8; q++) acc[q] *= sc;
            m = a;
        }
        float w = __expf(a - m);
        ssum += w;
        uint4 u = *reinterpret_cast<const uint4*>(
            &g_xp1h[(size_t)s * 256 + lane * 8]);
        float2 f0 = __half22float2(*reinterpret_cast<__half2*>(&u.x));
        float2 f1 = __half22float2(*reinterpret_cast<__half2*>(&u.y));
        float2 f2 = __half22float2(*reinterpret_cast<__half2*>(&u.z));
        float2 f3 = __half22float2(*reinterpret_cast<__half2*>(&u.w));
        acc[0] = fmaf(w, f0.x, acc[0]);
        acc[1] = fmaf(w, f0.y, acc[1]);
        acc[2] = fmaf(w, f1.x, acc[2]);
        acc[3] = fmaf(w, f1.y, acc[3]);
        acc[4] = fmaf(w, f2.x, acc[4]);
        acc[5] = fmaf(w, f2.y, acc[5]);
        acc[6] = fmaf(w, f3.x, acc[6]);
        acc[7] = fmaf(w, f3.y, acc[7]);
    }
    float inv = 1.f / ssum;
    int col = lane * 8;
    float o[8];
    #pragma unroll
    for (int q = 0; q < 8; q++) {
        float x = acc[q] * inv + b1[col + q];
        o[q] = (x > 0.f) ? x : expm1f(x);   // elu
    }
    __half2* dst = reinterpret_cast<__half2*>(&g_h16[(size_t)node * 256 + col]);
    dst[0] = __floats2half2_rn(o[0], o[1]);
    dst[1] = __floats2half2_rn(o[2], o[3]);
    dst[2] = __floats2half2_rn(o[4], o[5]);
    dst[3] = __floats2half2_rn(o[6], o[7]);
}

// ---------------- layer2 aggregation ---------------------------------------
__global__ void agg2_kernel(const float* __restrict__ b2,
                            float* __restrict__ out, int n) {
    int node = blockIdx.x * 8 + (threadIdx.x >> 5);
    if (node >= n) return;
    int lane = threadIdx.x & 31;
    int beg = g_offs[node], end = g_offs[node + 1];
    float adn = g_ald2[node];
    float m = -1e30f, ssum = 0.f, ax = 0.f, ay = 0.f;
    for (int j = beg; j < end; j++) {
        int s = g_ssrc[j];
        float a = g_als2[s] + adn;
        a = (a > 0.f) ? a : 0.2f * a;
        if (a > m) {
            float sc = __expf(m - a);
            ax *= sc; ay *= sc; ssum *= sc; m = a;
        }
        float w = __expf(a - m);
        ssum += w;
        float2 v = __half22float2(*reinterpret_cast<const __half2*>(
            &g_xp2h[(size_t)s * 64 + lane * 2]));
        ax = fmaf(w, v.x, ax);
        ay = fmaf(w, v.y, ay);
    }
    float inv = 1.f / ssum;
    int col = lane * 2;
    out[(size_t)node * 64 + col] =
        ax * inv + b2[col] + g_skip[(size_t)node * 64 + col];
    out[(size_t)node * 64 + col + 1] =
        ay * inv + b2[col + 1] + g_skip[(size_t)node * 64 + col + 1];
}

// ---------------- launch ---------------------------------------------------
extern "C" void kernel_launch(void* const* d_in, const int* in_sizes, int n_in,
                              void* d_out, int out_size) {
    const float* x_clean  = (const float*)d_in[0];
    const float* x_noised = (const float*)d_in[1];
    const int*   esrc     = (const int*)d_in[2];
    const int*   edst     = (const int*)d_in[3];
    const float* W1  = (const float*)d_in[4];
    const float* as1 = (const float*)d_in[5];
    const float* ad1 = (const float*)d_in[6];
    const float* b1  = (const float*)d_in[7];
    const float* W2  = (const float*)d_in[8];
    const float* as2 = (const float*)d_in[9];
    const float* ad2 = (const float*)d_in[10];
    const float* b2  = (const float*)d_in[11];
    float* out = (float*)d_out;

    int N = in_sizes[0] / 256;  // 50000
    int E = in_sizes[2];        // 800000

    const int SMB = (3 * 128 * 72 + 3 * 64 * 72) * 2;  // 82944 B
    cudaFuncSetAttribute(gemm_f16<0, true>,  cudaFuncAttributeMaxDynamicSharedMemorySize, SMB);
    cudaFuncSetAttribute(gemm_f16<1, true>,  cudaFuncAttributeMaxDynamicSharedMemorySize, SMB);
    cudaFuncSetAttribute(gemm_f16<2, false>, cudaFuncAttributeMaxDynamicSharedMemorySize, SMB);

    int nb = (N + 255) / 256;       // 196
    int mtiles = (N + 127) / 128;   // 391

    // Launch order: profiler samples launch #4 -> hot GEMM there.
    cvt_kernel<<<(NN * 256 / 4 + 255) / 256, 256>>>(
        x_noised, x_clean, W1, W2, as1, ad1, as2, ad2);                          // 1
    count_kernel<<<(E + 255) / 256, 256>>>(edst, E);                             // 2
    scan_local_kernel<<<nb, 256>>>(N);                                           // 3
    gemm_f16<0, true><<<dim3(mtiles, 5), 256, SMB>>>(0, 0, nullptr, 1, N, 256, 0); // 4: xp1 + logits1
    gemm_f16<1, true><<<dim3(mtiles, 4), 256, SMB>>>(1, 0, b1, 2, N, 256, -1);     // 5: hs16
    gemm_f16<2, false><<<dim3(mtiles, 1), 256, SMB>>>(2, 1, b2, 3, N, 64, -1);     // 6: skip
    scan_bsum_kernel<<<1, 256>>>(nb, N);                                         // 7
    scan_add_place_kernel<<<nb, 256>>>(N);                                       // 8
    scatter_kernel<<<(E + 255) / 256, 256>>>(esrc, edst, E);                     // 9

    // layer 1 attention
    agg1_kernel<<<(N + 7) / 8, 256>>>(b1, N);                                    // 10

    // layer 2
    gemm_f16<0, true><<<dim3(mtiles, 2), 256, SMB>>>(3, 1, nullptr, 4, N, 64, 1); // 11: xp2 + logits2
    agg2_kernel<<<(N + 7) / 8, 256>>>(b2, out, N);                               // 12
}

// round 8
// speedup vs baseline: 2.8208x; 1.0466x over previous
#include <cuda_runtime.h>
#include <cuda_fp16.h>
#include <cstdint>
#include <cstddef>

#define NN 50000
#define EE 800000
#define ET (EE + NN)

// ---------------- scratch (device globals; no allocation allowed) ----------
__device__ __align__(16) __half g_xp1h[(size_t)NN * 256];  // x_noised @ W1 (fp16)
__device__ __align__(16) __half g_xp2h[(size_t)NN * 64];   // h @ W2 (fp16)
__device__ __align__(16) float  g_skip[(size_t)NN * 64];
__device__ __align__(16) __half g_xa16[(size_t)NN * 256];  // fp16 x_noised
__device__ __align__(16) __half g_xc16[(size_t)NN * 256];  // fp16 x_clean
__device__ __align__(16) __half g_h16[(size_t)NN * 256];   // fp16 elu(layer1)
__device__ __align__(16) __half g_hs16[(size_t)NN * 256];  // fp16 relu(x_clean@W1+b1)
__device__ __align__(16) __half g_w1t16[320 * 256];        // W1^T fp16 [n][k] + 8 aug rows
__device__ __align__(16) __half g_w2t16[128 * 256];        // W2^T fp16 [n][k] + 2 aug rows
__device__ __align__(16) float g_als1[(size_t)NN * 4];
__device__ __align__(16) float g_ald1[(size_t)NN * 4];
__device__ __align__(16) float g_als2[NN];
__device__ __align__(16) float g_ald2[NN];
__device__ int g_deg[NN];
__device__ int g_offs[NN + 1];
__device__ int g_cur[NN];
__device__ int g_ssrc[ET];
__device__ int g_bsum[256];
__device__ int g_bpre[256];

// ------- fp16 conversion + weight transpose + augmented logit columns ------
__global__ void cvt_kernel(const float* __restrict__ xn,
                           const float* __restrict__ xc,
                           const float* __restrict__ W1,
                           const float* __restrict__ W2,
                           const float* __restrict__ as1,
                           const float* __restrict__ ad1,
                           const float* __restrict__ as2,
                           const float* __restrict__ ad2) {
    int i = blockIdx.x * 256 + threadIdx.x;
    if (i < (NN * 256) / 4) {
        float4 a = reinterpret_cast<const float4*>(xn)[i];
        float4 b = reinterpret_cast<const float4*>(xc)[i];
        reinterpret_cast<__half2*>(g_xa16)[i * 2]     = __floats2half2_rn(a.x, a.y);
        reinterpret_cast<__half2*>(g_xa16)[i * 2 + 1] = __floats2half2_rn(a.z, a.w);
        reinterpret_cast<__half2*>(g_xc16)[i * 2]     = __floats2half2_rn(b.x, b.y);
        reinterpret_cast<__half2*>(g_xc16)[i * 2 + 1] = __floats2half2_rn(b.z, b.w);
    }
    if (i < 256 * 256) {
        int k = i >> 8, n = i & 255;
        g_w1t16[n * 256 + k] = __float2half_rn(W1[k * 256 + n]);
    }
    if (i < 256 * 64) {
        int k = i >> 6, n = i & 63;
        g_w2t16[n * 256 + k] = __float2half_rn(W2[k * 64 + n]);
    }
    // augmented layer1 logit columns
    if (i < 256 * 8) {
        int k = i >> 3, j = i & 7;
        int h = j & 3;
        const float* av = (j < 4) ? as1 : ad1;
        float s = 0.f;
        #pragma unroll 8
        for (int c = 0; c < 64; c++)
            s += W1[k * 256 + h * 64 + c] * av[h * 64 + c];
        g_w1t16[(256 + j) * 256 + k] = __float2half_rn(s);
    }
    // augmented layer2 logit columns
    if (i < 256 * 2) {
        int k = i >> 1, j = i & 1;
        const float* av = j ? ad2 : as2;
        float s = 0.f;
        #pragma unroll 8
        for (int c = 0; c < 64; c++)
            s += W2[k * 64 + c] * av[c];
        g_w2t16[(64 + j) * 256 + k] = __float2half_rn(s);
    }
}

// ---------------- CSR build ------------------------------------------------
__global__ void init_deg_kernel(int n) {
    int i = blockIdx.x * blockDim.x + threadIdx.x;
    if (i < n) g_deg[i] = 1;   // self-loop
}

__global__ void count_kernel(const int* __restrict__ edst, int e) {
    int i = blockIdx.x * blockDim.x + threadIdx.x;
    if (i < e) atomicAdd(&g_deg[edst[i]], 1);
}

__global__ void scan_local_kernel(int n) {
    __shared__ int ws[9];
    int tid = threadIdx.x, lane = tid & 31, w = tid >> 5;
    int i = blockIdx.x * 256 + tid;
    int v = (i < n) ? g_deg[i] : 0;
    int x = v;
    #pragma unroll
    for (int o = 1; o < 32; o <<= 1) {
        int y = __shfl_up_sync(0xffffffffu, x, o);
        if (lane >= o) x += y;
    }
    if (lane == 31) ws[w] = x;
    __syncthreads();
    if (tid == 0) {
        int s = 0;
        #pragma unroll
        for (int q = 0; q < 8; q++) { int t = ws[q]; ws[q] = s; s += t; }
        g_bsum[blockIdx.x] = s;
    }
    __syncthreads();
    if (i < n) g_offs[i] = ws[w] + x - v;
}

__global__ void scan_bsum_kernel(int nb, int n) {
    __shared__ int wtot[8];
    int tid = threadIdx.x, lane = tid & 31, w = tid >> 5;
    int v = (tid < nb) ? g_bsum[tid] : 0;
    int x = v;
    #pragma unroll
    for (int o = 1; o < 32; o <<= 1) {
        int y = __shfl_up_sync(0xffffffffu, x, o);
        if (lane >= o) x += y;
    }
    if (lane == 31) wtot[w] = x;
    __syncthreads();
    int pre = 0;
    #pragma unroll
    for (int q = 0; q < 8; q++) pre += (q < w) ? wtot[q] : 0;
    if (tid < nb) g_bpre[tid] = pre + x - v;
    if (tid == nb - 1) g_offs[n] = pre + x;
}

__global__ void scan_add_place_kernel(int n) {
    int i = blockIdx.x * 256 + threadIdx.x;
    if (i < n) {
        int o = g_offs[i] + (blockIdx.x > 0 ? g_bpre[blockIdx.x] : 0);
        g_offs[i] = o;
        g_ssrc[o] = i;       // self-loop first
        g_cur[i] = o + 1;
    }
}

__global__ void scatter_kernel(const int* __restrict__ esrc,
                               const int* __restrict__ edst, int e) {
    int i = blockIdx.x * blockDim.x + threadIdx.x;
    if (i < e) {
        int d = edst[i];
        int pos = atomicAdd(&g_cur[d], 1);
        g_ssrc[pos] = esrc[i];
    }
}

// ---------------- FP16 tensor-core GEMM, 3-stage cp.async + ldmatrix -------
__device__ __forceinline__ uint32_t smem_u32(const void* p) {
    uint32_t a;
    asm("{ .reg .u64 t; cvta.to.shared.u64 t, %1; cvt.u32.u64 %0, t; }"
        : "=r"(a) : "l"(p));
    return a;
}
__device__ __forceinline__ void cp16(uint32_t dst, const void* src, int srcsz) {
    asm volatile("cp.async.cg.shared.global [%0], [%1], 16, %2;"
                 :: "r"(dst), "l"(src), "r"(srcsz));
}
__device__ __forceinline__ void cp_commit() {
    asm volatile("cp.async.commit_group;");
}
template <int N>
__device__ __forceinline__ void cp_wait() {
    asm volatile("cp.async.wait_group %0;" :: "n"(N));
}
__device__ __forceinline__ void ldsm_x4(unsigned& r0, unsigned& r1,
                                        unsigned& r2, unsigned& r3, uint32_t a) {
    asm volatile("ldmatrix.sync.aligned.m8n8.x4.shared.b16 {%0,%1,%2,%3}, [%4];"
                 : "=r"(r0), "=r"(r1), "=r"(r2), "=r"(r3) : "r"(a));
}
__device__ __forceinline__ void mma_f16(float* c, const unsigned* a,
                                        const unsigned* b) {
    asm volatile(
        "mma.sync.aligned.m16n8k16.row.col.f32.f16.f16.f32 "
        "{%0,%1,%2,%3}, {%4,%5,%6,%7}, {%8,%9}, {%0,%1,%2,%3};\n"
        : "+f"(c[0]), "+f"(c[1]), "+f"(c[2]), "+f"(c[3])
        : "r"(a[0]), "r"(a[1]), "r"(a[2]), "r"(a[3]), "r"(b[0]), "r"(b[1]));
}

// C[M,NC] = A16[M,256] @ B16t[NC(+aug),256]^T. Tile 128x64x64, 8 warps, 3 stages.
template <int EPI, bool C16>
__global__ void __launch_bounds__(256) gemm_f16(
    int asel, int bsel, const float* __restrict__ bias, int csel,
    int M, int NC, int augsel) {
    const __half* A = (asel == 0) ? g_xa16
                    : (asel == 1) ? g_xc16
                    : (asel == 2) ? g_hs16
                                  : g_h16;
    const __half* Bt = bsel ? g_w2t16 : g_w1t16;
    __half* Ch = (csel == 1) ? g_xp1h : (csel == 2) ? g_hs16 : g_xp2h;
    float* Cf = g_skip;

    extern __shared__ __half dynsm[];
    __half* As = dynsm;
    __half* Bs = dynsm + 3 * 128 * 72;
    const int ASTG = 128 * 72, BSTG = 64 * 72;

    int tid = threadIdx.x;
    int wid = tid >> 5, lane = tid & 31;
    int g = lane >> 2, t4 = lane & 3;
    int wm = (wid >> 1) * 32;
    int wn = (wid & 1) * 32;
    int m0 = blockIdx.x * 128;
    int n0 = blockIdx.y * 64;
    bool isAug = (n0 >= NC);

    uint32_t aA = smem_u32(As), aB = smem_u32(Bs);

    int a_row_off = (lane & 7) + ((lane >> 3) & 1) * 8;
    int a_col_off = ((lane >> 4) & 1) * 8;
    int b_row_off = (lane & 7) + ((lane >> 4) & 1) * 8;
    int b_col_off = ((lane >> 3) & 1) * 8;

    float acc[2][4][4];
    #pragma unroll
    for (int mt = 0; mt < 2; mt++)
        #pragma unroll
        for (int nt = 0; nt < 4; nt++)
            #pragma unroll
            for (int q = 0; q < 4; q++) acc[mt][nt][q] = 0.f;

    auto load_chunk = [&](int ch, int st) {
        int k0 = ch * 64;
        #pragma unroll
        for (int i = 0; i < 4; i++) {
            int lin = tid + i * 256;
            int row = lin >> 3, seg = lin & 7;
            uint32_t dst = aA + (uint32_t)(st * ASTG + row * 72 + seg * 8) * 2u;
            const __half* src = &A[(size_t)(m0 + row) * 256 + k0 + seg * 8];
            cp16(dst, src, (m0 + row < M) ? 16 : 0);
        }
        #pragma unroll
        for (int i = 0; i < 2; i++) {
            int lin = tid + i * 256;
            int row = lin >> 3, seg = lin & 7;
            uint32_t dst = aB + (uint32_t)(st * BSTG + row * 72 + seg * 8) * 2u;
            const __half* src = &Bt[(size_t)(n0 + row) * 256 + k0 + seg * 8];
            cp16(dst, src, 16);
        }
        cp_commit();
    };

    load_chunk(0, 0);
    load_chunk(1, 1);

    #pragma unroll
    for (int ch = 0; ch < 4; ch++) {
        if (ch < 3) cp_wait<1>(); else cp_wait<0>();
        __syncthreads();

        int st = ch % 3;
        uint32_t baseA = aA + (uint32_t)(st * ASTG) * 2u;
        uint32_t baseB = aB + (uint32_t)(st * BSTG) * 2u;
        #pragma unroll
        for (int ks = 0; ks < 4; ks++) {
            int kb = ks * 16;
            unsigned a[2][4], b[4][2];
            #pragma unroll
            for (int mt = 0; mt < 2; mt++) {
                uint32_t ad = baseA +
                    (uint32_t)((wm + mt * 16 + a_row_off) * 72 + kb + a_col_off) * 2u;
                ldsm_x4(a[mt][0], a[mt][1], a[mt][2], a[mt][3], ad);
            }
            #pragma unroll
            for (int p = 0; p < 2; p++) {
                uint32_t bd = baseB +
                    (uint32_t)((wn + p * 16 + b_row_off) * 72 + kb + b_col_off) * 2u;
                ldsm_x4(b[2 * p][0], b[2 * p][1], b[2 * p + 1][0], b[2 * p + 1][1], bd);
            }
            #pragma unroll
            for (int mt = 0; mt < 2; mt++)
                #pragma unroll
                for (int nt = 0; nt < 4; nt++)
                    mma_f16(acc[mt][nt], a[mt], b[nt]);
        }
        if (ch + 2 < 4) load_chunk(ch + 2, (ch + 2) % 3);
    }

    #pragma unroll
    for (int mt = 0; mt < 2; mt++) {
        #pragma unroll
        for (int half = 0; half < 2; half++) {
            int row = m0 + wm + mt * 16 + g + half * 8;
            if (row >= M) continue;
            #pragma unroll
            for (int nt = 0; nt < 4; nt++) {
                int col = n0 + wn + nt * 8 + 2 * t4;
                float v0 = acc[mt][nt][half * 2 + 0];
                float v1 = acc[mt][nt][half * 2 + 1];
                if (isAug) {
                    int c = col - NC;
                    if (c < 8) {
                        if (augsel == 0) {
                            if (c < 4) g_als1[(size_t)row * 4 + c] = v0;
                            else       g_ald1[(size_t)row * 4 + c - 4] = v0;
                            int c1 = c + 1;
                            if (c1 < 4) g_als1[(size_t)row * 4 + c1] = v1;
                            else        g_ald1[(size_t)row * 4 + c1 - 4] = v1;
                        } else {
                            if (c == 0) { g_als2[row] = v0; g_ald2[row] = v1; }
                        }
                    }
                    continue;
                }
                if (EPI) {
                    v0 += bias[col];
                    v1 += bias[col + 1];
                    if (EPI == 1) {
                        v0 = fmaxf(v0, 0.f);
                        v1 = fmaxf(v1, 0.f);
                    }
                }
                if (C16) {
                    *reinterpret_cast<__half2*>(&Ch[(size_t)row * NC + col]) =
                        __floats2half2_rn(v0, v1);
                } else {
                    *reinterpret_cast<float2*>(&Cf[(size_t)row * NC + col]) =
                        make_float2(v0, v1);
                }
            }
        }
    }
}

// ---------------- layer1 aggregation: one warp per node, all 4 heads -------
__global__ void agg1_kernel(const float* __restrict__ b1, int n) {
    int node = blockIdx.x * 8 + (threadIdx.x >> 5);
    if (node >= n) return;
    int lane = threadIdx.x & 31;
    int h = lane >> 3;
    int beg = g_offs[node], end = g_offs[node + 1];
    float adn = g_ald1[node * 4 + h];
    float m = -1e30f, ssum = 0.f;
    float acc[8];
    #pragma unroll
    for (int q = 0; q < 8; q++) acc[q] = 0.f;

    for (int j = beg; j < end; j++) {
        int s = g_ssrc[j];
        float a = g_als1[s * 4 + h] + adn;
        a = (a > 0.f) ? a : 0.2f * a;
        if (a > m) {
            float sc = __expf(m - a);
            ssum *= sc;
            #pragma unroll
            for (int q = 0; q < 8; q++) acc[q] *= sc;
            m = a;
        }
        float w = __expf(a - m);
        ssum += w;
        uint4 u = *reinterpret_cast<const uint4*>(
            &g_xp1h[(size_t)s * 256 + lane * 8]);
        float2 f0 = __half22float2(*reinterpret_cast<__half2*>(&u.x));
        float2 f1 = __half22float2(*reinterpret_cast<__half2*>(&u.y));
        float2 f2 = __half22float2(*reinterpret_cast<__half2*>(&u.z));
        float2 f3 = __half22float2(*reinterpret_cast<__half2*>(&u.w));
        acc[0] = fmaf(w, f0.x, acc[0]);
        acc[1] = fmaf(w, f0.y, acc[1]);
        acc[2] = fmaf(w, f1.x, acc[2]);
        acc[3] = fmaf(w, f1.y, acc[3]);
        acc[4] = fmaf(w, f2.x, acc[4]);
        acc[5] = fmaf(w, f2.y, acc[5]);
        acc[6] = fmaf(w, f3.x, acc[6]);
        acc[7] = fmaf(w, f3.y, acc[7]);
    }
    float inv = 1.f / ssum;
    int col = lane * 8;
    float o[8];
    #pragma unroll
    for (int q = 0; q < 8; q++) {
        float x = acc[q] * inv + b1[col + q];
        o[q] = (x > 0.f) ? x : expm1f(x);   // elu
    }
    __half2* dst = reinterpret_cast<__half2*>(&g_h16[(size_t)node * 256 + col]);
    dst[0] = __floats2half2_rn(o[0], o[1]);
    dst[1] = __floats2half2_rn(o[2], o[3]);
    dst[2] = __floats2half2_rn(o[4], o[5]);
    dst[3] = __floats2half2_rn(o[6], o[7]);
}

// ---------------- layer2 aggregation ---------------------------------------
__global__ void agg2_kernel(const float* __restrict__ b2,
                            float* __restrict__ out, int n) {
    int node = blockIdx.x * 8 + (threadIdx.x >> 5);
    if (node >= n) return;
    int lane = threadIdx.x & 31;
    int beg = g_offs[node], end = g_offs[node + 1];
    float adn = g_ald2[node];
    float m = -1e30f, ssum = 0.f, ax = 0.f, ay = 0.f;
    for (int j = beg; j < end; j++) {
        int s = g_ssrc[j];
        float a = g_als2[s] + adn;
        a = (a > 0.f) ? a : 0.2f * a;
        if (a > m) {
            float sc = __expf(m - a);
            ax *= sc; ay *= sc; ssum *= sc; m = a;
        }
        float w = __expf(a - m);
        ssum += w;
        float2 v = __half22float2(*reinterpret_cast<const __half2*>(
            &g_xp2h[(size_t)s * 64 + lane * 2]));
        ax = fmaf(w, v.x, ax);
        ay = fmaf(w, v.y, ay);
    }
    float inv = 1.f / ssum;
    int col = lane * 2;
    out[(size_t)node * 64 + col] =
        ax * inv + b2[col] + g_skip[(size_t)node * 64 + col];
    out[(size_t)node * 64 + col + 1] =
        ay * inv + b2[col + 1] + g_skip[(size_t)node * 64 + col + 1];
}

// ---------------- launch (two streams, event fork/join) ---------------------
extern "C" void kernel_launch(void* const* d_in, const int* in_sizes, int n_in,
                              void* d_out, int out_size) {
    const float* x_clean  = (const float*)d_in[0];
    const float* x_noised = (const float*)d_in[1];
    const int*   esrc     = (const int*)d_in[2];
    const int*   edst     = (const int*)d_in[3];
    const float* W1  = (const float*)d_in[4];
    const float* as1 = (const float*)d_in[5];
    const float* ad1 = (const float*)d_in[6];
    const float* b1  = (const float*)d_in[7];
    const float* W2  = (const float*)d_in[8];
    const float* as2 = (const float*)d_in[9];
    const float* ad2 = (const float*)d_in[10];
    const float* b2  = (const float*)d_in[11];
    float* out = (float*)d_out;

    int N = in_sizes[0] / 256;  // 50000
    int E = in_sizes[2];        // 800000

    static cudaStream_t s1 = nullptr;
    static cudaEvent_t evRoot, evCvt, evCsr, evSkip;
    if (s1 == nullptr) {
        cudaStreamCreateWithFlags(&s1, cudaStreamNonBlocking);
        cudaEventCreateWithFlags(&evRoot, cudaEventDisableTiming);
        cudaEventCreateWithFlags(&evCvt,  cudaEventDisableTiming);
        cudaEventCreateWithFlags(&evCsr,  cudaEventDisableTiming);
        cudaEventCreateWithFlags(&evSkip, cudaEventDisableTiming);
        const int SMBi = (3 * 128 * 72 + 3 * 64 * 72) * 2;
        cudaFuncSetAttribute(gemm_f16<0, true>,  cudaFuncAttributeMaxDynamicSharedMemorySize, SMBi);
        cudaFuncSetAttribute(gemm_f16<1, true>,  cudaFuncAttributeMaxDynamicSharedMemorySize, SMBi);
        cudaFuncSetAttribute(gemm_f16<2, false>, cudaFuncAttributeMaxDynamicSharedMemorySize, SMBi);
    }
    const int SMB = (3 * 128 * 72 + 3 * 64 * 72) * 2;  // 82944 B

    int nb = (N + 255) / 256;       // 196
    int mtiles = (N + 127) / 128;   // 391

    // fork s1 from capture stream
    cudaEventRecord(evRoot, 0);
    cudaStreamWaitEvent(s1, evRoot, 0);

    // s0: cvt -> xp1 GEMM (launch #4 overall for the profiler)
    cvt_kernel<<<(NN * 256 / 4 + 255) / 256, 256>>>(
        x_noised, x_clean, W1, W2, as1, ad1, as2, ad2);                          // 1
    cudaEventRecord(evCvt, 0);

    // s1: CSR build chain (independent of cvt)
    init_deg_kernel<<<nb, 256, 0, s1>>>(N);                                      // 2
    count_kernel<<<(E + 255) / 256, 256, 0, s1>>>(edst, E);                      // 3

    gemm_f16<0, true><<<dim3(mtiles, 5), 256, SMB>>>(0, 0, nullptr, 1, N, 256, 0); // 4: xp1+logits1

    scan_local_kernel<<<nb, 256, 0, s1>>>(N);                                    // 5
    scan_bsum_kernel<<<1, 256, 0, s1>>>(nb, N);                                  // 6
    scan_add_place_kernel<<<nb, 256, 0, s1>>>(N);                                // 7
    scatter_kernel<<<(E + 255) / 256, 256, 0, s1>>>(esrc, edst, E);              // 8
    cudaEventRecord(evCsr, s1);

    // s1: skip path GEMMs (need cvt)
    cudaStreamWaitEvent(s1, evCvt, 0);
    gemm_f16<1, true><<<dim3(mtiles, 4), 256, SMB, s1>>>(1, 0, b1, 2, N, 256, -1);  // 9: hs16
    gemm_f16<2, false><<<dim3(mtiles, 1), 256, SMB, s1>>>(2, 1, b2, 3, N, 64, -1);  // 10: skip
    cudaEventRecord(evSkip, s1);

    // s0: agg1 (needs xp1 + CSR), then layer 2
    cudaStreamWaitEvent(0, evCsr, 0);
    agg1_kernel<<<(N + 7) / 8, 256>>>(b1, N);                                    // 11
    gemm_f16<0, true><<<dim3(mtiles, 2), 256, SMB>>>(3, 1, nullptr, 4, N, 64, 1);   // 12: xp2+logits2
    cudaStreamWaitEvent(0, evSkip, 0);
    agg2_kernel<<<(N + 7) / 8, 256>>>(b2, out, N);                               // 13
}

// round 9
// speedup vs baseline: 2.8976x; 1.0272x over previous
#include <cuda_runtime.h>
#include <cuda_fp16.h>
#include <cstdint>
#include <cstddef>

#define NN 50000
#define EE 800000
#define ET (EE + NN)

// ---------------- scratch (device globals; no allocation allowed) ----------
__device__ __align__(16) __half g_xp1h[(size_t)NN * 256];  // x_noised @ W1 (fp16)
__device__ __align__(16) __half g_xp2h[(size_t)NN * 64];   // h @ W2 (fp16)
__device__ __align__(16) float  g_skip[(size_t)NN * 64];
__device__ __align__(16) __half g_xa16[(size_t)NN * 256];  // fp16 x_noised
__device__ __align__(16) __half g_xc16[(size_t)NN * 256];  // fp16 x_clean
__device__ __align__(16) __half g_h16[(size_t)NN * 256];   // fp16 elu(layer1)
__device__ __align__(16) __half g_hs16[(size_t)NN * 256];  // fp16 relu(x_clean@W1+b1)
__device__ __align__(16) __half g_w1t16[384 * 256];        // W1^T fp16 + 8 aug rows (padded)
__device__ __align__(16) __half g_w2t16[128 * 256];        // W2^T fp16 + 2 aug rows (padded)
__device__ __align__(16) float g_als1[(size_t)NN * 4];
__device__ __align__(16) float g_ald1[(size_t)NN * 4];
__device__ __align__(16) float g_als2[NN];
__device__ __align__(16) float g_ald2[NN];
__device__ int g_deg[NN];
__device__ int g_offs[NN + 1];
__device__ int g_cur[NN];
__device__ int g_ssrc[ET];
__device__ int g_bsum[256];
__device__ int g_bpre[256];

// ------- fp16 conversion + weight transpose + augmented logit columns ------
__global__ void cvt_kernel(const float* __restrict__ xn,
                           const float* __restrict__ xc,
                           const float* __restrict__ W1,
                           const float* __restrict__ W2,
                           const float* __restrict__ as1,
                           const float* __restrict__ ad1,
                           const float* __restrict__ as2,
                           const float* __restrict__ ad2) {
    int i = blockIdx.x * 256 + threadIdx.x;
    if (i < (NN * 256) / 4) {
        float4 a = reinterpret_cast<const float4*>(xn)[i];
        float4 b = reinterpret_cast<const float4*>(xc)[i];
        reinterpret_cast<__half2*>(g_xa16)[i * 2]     = __floats2half2_rn(a.x, a.y);
        reinterpret_cast<__half2*>(g_xa16)[i * 2 + 1] = __floats2half2_rn(a.z, a.w);
        reinterpret_cast<__half2*>(g_xc16)[i * 2]     = __floats2half2_rn(b.x, b.y);
        reinterpret_cast<__half2*>(g_xc16)[i * 2 + 1] = __floats2half2_rn(b.z, b.w);
    }
    if (i < 256 * 256) {
        int k = i >> 8, n = i & 255;
        g_w1t16[n * 256 + k] = __float2half_rn(W1[k * 256 + n]);
    }
    if (i < 256 * 64) {
        int k = i >> 6, n = i & 63;
        g_w2t16[n * 256 + k] = __float2half_rn(W2[k * 64 + n]);
    }
    // augmented layer1 logit columns
    if (i < 256 * 8) {
        int k = i >> 3, j = i & 7;
        int h = j & 3;
        const float* av = (j < 4) ? as1 : ad1;
        float s = 0.f;
        #pragma unroll 8
        for (int c = 0; c < 64; c++)
            s += W1[k * 256 + h * 64 + c] * av[h * 64 + c];
        g_w1t16[(256 + j) * 256 + k] = __float2half_rn(s);
    }
    // augmented layer2 logit columns
    if (i < 256 * 2) {
        int k = i >> 1, j = i & 1;
        const float* av = j ? ad2 : as2;
        float s = 0.f;
        #pragma unroll 8
        for (int c = 0; c < 64; c++)
            s += W2[k * 64 + c] * av[c];
        g_w2t16[(64 + j) * 256 + k] = __float2half_rn(s);
    }
}

// ---------------- CSR build ------------------------------------------------
__global__ void init_deg_kernel(int n) {
    int i = blockIdx.x * blockDim.x + threadIdx.x;
    if (i < n) g_deg[i] = 1;   // self-loop
}

__global__ void count_kernel(const int* __restrict__ edst, int e) {
    int i = blockIdx.x * blockDim.x + threadIdx.x;
    if (i < e) atomicAdd(&g_deg[edst[i]], 1);
}

__global__ void scan_local_kernel(int n) {
    __shared__ int ws[9];
    int tid = threadIdx.x, lane = tid & 31, w = tid >> 5;
    int i = blockIdx.x * 256 + tid;
    int v = (i < n) ? g_deg[i] : 0;
    int x = v;
    #pragma unroll
    for (int o = 1; o < 32; o <<= 1) {
        int y = __shfl_up_sync(0xffffffffu, x, o);
        if (lane >= o) x += y;
    }
    if (lane == 31) ws[w] = x;
    __syncthreads();
    if (tid == 0) {
        int s = 0;
        #pragma unroll
        for (int q = 0; q < 8; q++) { int t = ws[q]; ws[q] = s; s += t; }
        g_bsum[blockIdx.x] = s;
    }
    __syncthreads();
    if (i < n) g_offs[i] = ws[w] + x - v;
}

__global__ void scan_bsum_kernel(int nb, int n) {
    __shared__ int wtot[8];
    int tid = threadIdx.x, lane = tid & 31, w = tid >> 5;
    int v = (tid < nb) ? g_bsum[tid] : 0;
    int x = v;
    #pragma unroll
    for (int o = 1; o < 32; o <<= 1) {
        int y = __shfl_up_sync(0xffffffffu, x, o);
        if (lane >= o) x += y;
    }
    if (lane == 31) wtot[w] = x;
    __syncthreads();
    int pre = 0;
    #pragma unroll
    for (int q = 0; q < 8; q++) pre += (q < w) ? wtot[q] : 0;
    if (tid < nb) g_bpre[tid] = pre + x - v;
    if (tid == nb - 1) g_offs[n] = pre + x;
}

__global__ void scan_add_place_kernel(int n) {
    int i = blockIdx.x * 256 + threadIdx.x;
    if (i < n) {
        int o = g_offs[i] + (blockIdx.x > 0 ? g_bpre[blockIdx.x] : 0);
        g_offs[i] = o;
        g_ssrc[o] = i;       // self-loop first
        g_cur[i] = o + 1;
    }
}

__global__ void scatter_kernel(const int* __restrict__ esrc,
                               const int* __restrict__ edst, int e) {
    int i = blockIdx.x * blockDim.x + threadIdx.x;
    if (i < e) {
        int d = edst[i];
        int pos = atomicAdd(&g_cur[d], 1);
        g_ssrc[pos] = esrc[i];
    }
}

// ---------------- FP16 tensor-core GEMM, 128x128 tile, 2-stage cp.async ----
__device__ __forceinline__ uint32_t smem_u32(const void* p) {
    uint32_t a;
    asm("{ .reg .u64 t; cvta.to.shared.u64 t, %1; cvt.u32.u64 %0, t; }"
        : "=r"(a) : "l"(p));
    return a;
}
__device__ __forceinline__ void cp16(uint32_t dst, const void* src, int srcsz) {
    asm volatile("cp.async.cg.shared.global [%0], [%1], 16, %2;"
                 :: "r"(dst), "l"(src), "r"(srcsz));
}
__device__ __forceinline__ void cp_commit() {
    asm volatile("cp.async.commit_group;");
}
template <int N>
__device__ __forceinline__ void cp_wait() {
    asm volatile("cp.async.wait_group %0;" :: "n"(N));
}
__device__ __forceinline__ void ldsm_x4(unsigned& r0, unsigned& r1,
                                        unsigned& r2, unsigned& r3, uint32_t a) {
    asm volatile("ldmatrix.sync.aligned.m8n8.x4.shared.b16 {%0,%1,%2,%3}, [%4];"
                 : "=r"(r0), "=r"(r1), "=r"(r2), "=r"(r3) : "r"(a));
}
__device__ __forceinline__ void mma_f16(float* c, const unsigned* a,
                                        const unsigned* b) {
    asm volatile(
        "mma.sync.aligned.m16n8k16.row.col.f32.f16.f16.f32 "
        "{%0,%1,%2,%3}, {%4,%5,%6,%7}, {%8,%9}, {%0,%1,%2,%3};\n"
        : "+f"(c[0]), "+f"(c[1]), "+f"(c[2]), "+f"(c[3])
        : "r"(a[0]), "r"(a[1]), "r"(a[2]), "r"(a[3]), "r"(b[0]), "r"(b[1]));
}

// C[M,NC] = A16[M,256] @ B16t[rows,256]^T. Tile 128x128x64, 8 warps (2x4).
// Columns >= NC: aug logits (augsel 0=layer1, 1=layer2) or discarded.
// EPI: 0 none, 1 +bias relu, 2 +bias. C16: write fp16 else fp32 (skip).
template <int EPI, bool C16>
__global__ void __launch_bounds__(256, 2) gemm_f16(
    int asel, int bsel, const float* __restrict__ bias, int csel,
    int M, int NC, int augsel) {
    const __half* A = (asel == 0) ? g_xa16
                    : (asel == 1) ? g_xc16
                    : (asel == 2) ? g_hs16
                                  : g_h16;
    const __half* Bt = bsel ? g_w2t16 : g_w1t16;
    __half* Ch = (csel == 1) ? g_xp1h : (csel == 2) ? g_hs16 : g_xp2h;
    float* Cf = g_skip;

    // smem (halfs): As[2][128][72], Bs[2][128][72]
    extern __shared__ __half dynsm[];
    __half* As = dynsm;
    __half* Bs = dynsm + 2 * 128 * 72;
    const int ASTG = 128 * 72, BSTG = 128 * 72;

    int tid = threadIdx.x;
    int wid = tid >> 5, lane = tid & 31;
    int g = lane >> 2, t4 = lane & 3;
    int wm = (wid >> 2) * 64;        // 2 warps in m -> 64 rows each
    int wn = (wid & 3) * 32;         // 4 warps in n -> 32 cols each
    int m0 = blockIdx.x * 128;
    int n0 = blockIdx.y * 128;

    uint32_t aA = smem_u32(As), aB = smem_u32(Bs);

    int a_row_off = (lane & 7) + ((lane >> 3) & 1) * 8;
    int a_col_off = ((lane >> 4) & 1) * 8;
    int b_row_off = (lane & 7) + ((lane >> 4) & 1) * 8;
    int b_col_off = ((lane >> 3) & 1) * 8;

    float acc[4][4][4];
    #pragma unroll
    for (int mt = 0; mt < 4; mt++)
        #pragma unroll
        for (int nt = 0; nt < 4; nt++)
            #pragma unroll
            for (int q = 0; q < 4; q++) acc[mt][nt][q] = 0.f;

    auto load_chunk = [&](int ch, int st) {
        int k0 = ch * 64;
        #pragma unroll
        for (int i = 0; i < 4; i++) {
            int lin = tid + i * 256;
            int row = lin >> 3, seg = lin & 7;
            uint32_t dst = aA + (uint32_t)(st * ASTG + row * 72 + seg * 8) * 2u;
            const __half* src = &A[(size_t)(m0 + row) * 256 + k0 + seg * 8];
            cp16(dst, src, (m0 + row < M) ? 16 : 0);
        }
        #pragma unroll
        for (int i = 0; i < 4; i++) {
            int lin = tid + i * 256;
            int row = lin >> 3, seg = lin & 7;
            uint32_t dst = aB + (uint32_t)(st * BSTG + row * 72 + seg * 8) * 2u;
            const __half* src = &Bt[(size_t)(n0 + row) * 256 + k0 + seg * 8];
            cp16(dst, src, 16);
        }
        cp_commit();
    };

    load_chunk(0, 0);

    #pragma unroll
    for (int ch = 0; ch < 4; ch++) {
        int st = ch & 1;
        if (ch < 3) {
            load_chunk(ch + 1, st ^ 1);
            cp_wait<1>();
        } else {
            cp_wait<0>();
        }
        __syncthreads();

        uint32_t baseA = aA + (uint32_t)(st * ASTG) * 2u;
        uint32_t baseB = aB + (uint32_t)(st * BSTG) * 2u;
        #pragma unroll
        for (int ks = 0; ks < 4; ks++) {
            int kb = ks * 16;
            unsigned a[4][4], b[4][2];
            #pragma unroll
            for (int mt = 0; mt < 4; mt++) {
                uint32_t ad = baseA +
                    (uint32_t)((wm + mt * 16 + a_row_off) * 72 + kb + a_col_off) * 2u;
                ldsm_x4(a[mt][0], a[mt][1], a[mt][2], a[mt][3], ad);
            }
            #pragma unroll
            for (int p = 0; p < 2; p++) {
                uint32_t bd = baseB +
                    (uint32_t)((wn + p * 16 + b_row_off) * 72 + kb + b_col_off) * 2u;
                ldsm_x4(b[2 * p][0], b[2 * p][1], b[2 * p + 1][0], b[2 * p + 1][1], bd);
            }
            #pragma unroll
            for (int mt = 0; mt < 4; mt++)
                #pragma unroll
                for (int nt = 0; nt < 4; nt++)
                    mma_f16(acc[mt][nt], a[mt], b[nt]);
        }
        __syncthreads();
    }

    // epilogue (per-column guards for partial / aug tiles)
    #pragma unroll
    for (int mt = 0; mt < 4; mt++) {
        #pragma unroll
        for (int half = 0; half < 2; half++) {
            int row = m0 + wm + mt * 16 + g + half * 8;
            if (row >= M) continue;
            #pragma unroll
            for (int nt = 0; nt < 4; nt++) {
                int col = n0 + wn + nt * 8 + 2 * t4;
                float v0 = acc[mt][nt][half * 2 + 0];
                float v1 = acc[mt][nt][half * 2 + 1];
                int c = col - NC;
                if (c >= 0) {
                    if (augsel == 0 && c < 8) {
                        if (c < 4) g_als1[(size_t)row * 4 + c] = v0;
                        else       g_ald1[(size_t)row * 4 + c - 4] = v0;
                        int c1 = c + 1;
                        if (c1 < 4) g_als1[(size_t)row * 4 + c1] = v1;
                        else        g_ald1[(size_t)row * 4 + c1 - 4] = v1;
                    } else if (augsel == 1 && c == 0) {
                        g_als2[row] = v0; g_ald2[row] = v1;
                    }
                    continue;
                }
                if (EPI) {
                    v0 += bias[col];
                    v1 += bias[col + 1];
                    if (EPI == 1) {
                        v0 = fmaxf(v0, 0.f);
                        v1 = fmaxf(v1, 0.f);
                    }
                }
                if (C16) {
                    *reinterpret_cast<__half2*>(&Ch[(size_t)row * NC + col]) =
                        __floats2half2_rn(v0, v1);
                } else {
                    *reinterpret_cast<float2*>(&Cf[(size_t)row * NC + col]) =
                        make_float2(v0, v1);
                }
            }
        }
    }
}

// ---------------- layer1 aggregation: one warp per node, all 4 heads -------
__global__ void agg1_kernel(const float* __restrict__ b1, int n) {
    int node = blockIdx.x * 8 + (threadIdx.x >> 5);
    if (node >= n) return;
    int lane = threadIdx.x & 31;
    int h = lane >> 3;
    int beg = g_offs[node], end = g_offs[node + 1];
    float adn = g_ald1[node * 4 + h];
    float m = -1e30f, ssum = 0.f;
    float acc[8];
    #pragma unroll
    for (int q = 0; q < 8; q++) acc[q] = 0.f;

    for (int j = beg; j < end; j++) {
        int s = g_ssrc[j];
        float a = g_als1[s * 4 + h] + adn;
        a = (a > 0.f) ? a : 0.2f * a;
        if (a > m) {
            float sc = __expf(m - a);
            ssum *= sc;
            #pragma unroll
            for (int q = 0; q < 8; q++) acc[q] *= sc;
            m = a;
        }
        float w = __expf(a - m);
        ssum += w;
        uint4 u = *reinterpret_cast<const uint4*>(
            &g_xp1h[(size_t)s * 256 + lane * 8]);
        float2 f0 = __half22float2(*reinterpret_cast<__half2*>(&u.x));
        float2 f1 = __half22float2(*reinterpret_cast<__half2*>(&u.y));
        float2 f2 = __half22float2(*reinterpret_cast<__half2*>(&u.z));
        float2 f3 = __half22float2(*reinterpret_cast<__half2*>(&u.w));
        acc[0] = fmaf(w, f0.x, acc[0]);
        acc[1] = fmaf(w, f0.y, acc[1]);
        acc[2] = fmaf(w, f1.x, acc[2]);
        acc[3] = fmaf(w, f1.y, acc[3]);
        acc[4] = fmaf(w, f2.x, acc[4]);
        acc[5] = fmaf(w, f2.y, acc[5]);
        acc[6] = fmaf(w, f3.x, acc[6]);
        acc[7] = fmaf(w, f3.y, acc[7]);
    }
    float inv = 1.f / ssum;
    int col = lane * 8;
    float o[8];
    #pragma unroll
    for (int q = 0; q < 8; q++) {
        float x = acc[q] * inv + b1[col + q];
        o[q] = (x > 0.f) ? x : expm1f(x);   // elu
    }
    __half2* dst = reinterpret_cast<__half2*>(&g_h16[(size_t)node * 256 + col]);
    dst[0] = __floats2half2_rn(o[0], o[1]);
    dst[1] = __floats2half2_rn(o[2], o[3]);
    dst[2] = __floats2half2_rn(o[4], o[5]);
    dst[3] = __floats2half2_rn(o[6], o[7]);
}

// ---------------- layer2 aggregation ---------------------------------------
__global__ void agg2_kernel(const float* __restrict__ b2,
                            float* __restrict__ out, int n) {
    int node = blockIdx.x * 8 + (threadIdx.x >> 5);
    if (node >= n) return;
    int lane = threadIdx.x & 31;
    int beg = g_offs[node], end = g_offs[node + 1];
    float adn = g_ald2[node];
    float m = -1e30f, ssum = 0.f, ax = 0.f, ay = 0.f;
    for (int j = beg; j < end; j++) {
        int s = g_ssrc[j];
        float a = g_als2[s] + adn;
        a = (a > 0.f) ? a : 0.2f * a;
        if (a > m) {
            float sc = __expf(m - a);
            ax *= sc; ay *= sc; ssum *= sc; m = a;
        }
        float w = __expf(a - m);
        ssum += w;
        float2 v = __half22float2(*reinterpret_cast<const __half2*>(
            &g_xp2h[(size_t)s * 64 + lane * 2]));
        ax = fmaf(w, v.x, ax);
        ay = fmaf(w, v.y, ay);
    }
    float inv = 1.f / ssum;
    int col = lane * 2;
    out[(size_t)node * 64 + col] =
        ax * inv + b2[col] + g_skip[(size_t)node * 64 + col];
    out[(size_t)node * 64 + col + 1] =
        ay * inv + b2[col + 1] + g_skip[(size_t)node * 64 + col + 1];
}

// ---------------- launch (two streams, event fork/join) ---------------------
extern "C" void kernel_launch(void* const* d_in, const int* in_sizes, int n_in,
                              void* d_out, int out_size) {
    const float* x_clean  = (const float*)d_in[0];
    const float* x_noised = (const float*)d_in[1];
    const int*   esrc     = (const int*)d_in[2];
    const int*   edst     = (const int*)d_in[3];
    const float* W1  = (const float*)d_in[4];
    const float* as1 = (const float*)d_in[5];
    const float* ad1 = (const float*)d_in[6];
    const float* b1  = (const float*)d_in[7];
    const float* W2  = (const float*)d_in[8];
    const float* as2 = (const float*)d_in[9];
    const float* ad2 = (const float*)d_in[10];
    const float* b2  = (const float*)d_in[11];
    float* out = (float*)d_out;

    int N = in_sizes[0] / 256;  // 50000
    int E = in_sizes[2];        // 800000

    static cudaStream_t s1 = nullptr;
    static cudaEvent_t evRoot, evCvt, evCsr, evSkip;
    if (s1 == nullptr) {
        cudaStreamCreateWithFlags(&s1, cudaStreamNonBlocking);
        cudaEventCreateWithFlags(&evRoot, cudaEventDisableTiming);
        cudaEventCreateWithFlags(&evCvt,  cudaEventDisableTiming);
        cudaEventCreateWithFlags(&evCsr,  cudaEventDisableTiming);
        cudaEventCreateWithFlags(&evSkip, cudaEventDisableTiming);
        const int SMBi = (2 * 128 * 72 + 2 * 128 * 72) * 2;
        cudaFuncSetAttribute(gemm_f16<0, true>,  cudaFuncAttributeMaxDynamicSharedMemorySize, SMBi);
        cudaFuncSetAttribute(gemm_f16<1, true>,  cudaFuncAttributeMaxDynamicSharedMemorySize, SMBi);
        cudaFuncSetAttribute(gemm_f16<2, false>, cudaFuncAttributeMaxDynamicSharedMemorySize, SMBi);
    }
    const int SMB = (2 * 128 * 72 + 2 * 128 * 72) * 2;  // 73728 B

    int nb = (N + 255) / 256;       // 196
    int mtiles = (N + 127) / 128;   // 391

    // fork s1 from capture stream
    cudaEventRecord(evRoot, 0);
    cudaStreamWaitEvent(s1, evRoot, 0);

    // s0: cvt -> xp1 GEMM (launch #4 overall for the profiler)
    cvt_kernel<<<(NN * 256 / 4 + 255) / 256, 256>>>(
        x_noised, x_clean, W1, W2, as1, ad1, as2, ad2);                          // 1
    cudaEventRecord(evCvt, 0);

    // s1: CSR build chain (independent of cvt)
    init_deg_kernel<<<nb, 256, 0, s1>>>(N);                                      // 2
    count_kernel<<<(E + 255) / 256, 256, 0, s1>>>(edst, E);                      // 3

    gemm_f16<0, true><<<dim3(mtiles, 3), 256, SMB>>>(0, 0, nullptr, 1, N, 256, 0); // 4: xp1+logits1

    scan_local_kernel<<<nb, 256, 0, s1>>>(N);                                    // 5
    scan_bsum_kernel<<<1, 256, 0, s1>>>(nb, N);                                  // 6
    scan_add_place_kernel<<<nb, 256, 0, s1>>>(N);                                // 7
    scatter_kernel<<<(E + 255) / 256, 256, 0, s1>>>(esrc, edst, E);              // 8
    cudaEventRecord(evCsr, s1);

    // s1: skip path GEMMs (need cvt)
    cudaStreamWaitEvent(s1, evCvt, 0);
    gemm_f16<1, true><<<dim3(mtiles, 2), 256, SMB, s1>>>(1, 0, b1, 2, N, 256, -1);  // 9: hs16
    gemm_f16<2, false><<<dim3(mtiles, 1), 256, SMB, s1>>>(2, 1, b2, 3, N, 64, -1);  // 10: skip
    cudaEventRecord(evSkip, s1);

    // s0: agg1 (needs xp1 + CSR), then layer 2
    cudaStreamWaitEvent(0, evCsr, 0);
    agg1_kernel<<<(N + 7) / 8, 256>>>(b1, N);                                    // 11
    gemm_f16<0, true><<<dim3(mtiles, 1), 256, SMB>>>(3, 1, nullptr, 4, N, 64, 1);   // 12: xp2+logits2
    cudaStreamWaitEvent(0, evSkip, 0);
    agg2_kernel<<<(N + 7) / 8, 256>>>(b2, out, N);                               // 13
}